// round 9
// baseline (speedup 1.0000x reference)
#include <cuda_runtime.h>
#include <math.h>

#define Bsz 2
#define Ssz 2048
#define Dsz 1024
#define Hn  16
#define DHs 64
#define Mrows (Bsz*Ssz)

// Scratch (static device globals; no runtime allocation)
__device__ float g_xq[Mrows*Dsz];   // inputs, tf32-rounded + pi32-permuted cols
__device__ float g_xk[Mrows*Dsz];
__device__ float g_xv[Mrows*Dsz];
__device__ float g_wq[Dsz*Dsz];     // weights, tf32-rounded + pi64-permuted cols
__device__ float g_wk[Dsz*Dsz];
__device__ float g_wv[Dsz*Dsz];
__device__ float g_wo[Dsz*Dsz];
__device__ float g_q[Mrows*Dsz];    // [B,H,S,64]  tf32, plain dh
__device__ float g_k[Mrows*Dsz];    // [B,H,64,S]  TRANSPOSED (d-major), tf32
__device__ float g_v[Mrows*Dsz];    // [B,H,S,64]  tf32, dh -> pi64(dh)
__device__ float g_o[Mrows*Dsz];    // [M,1024]    tf32 + pi32-permuted cols

// ---------------------------------------------------------------------------
// helpers
// ---------------------------------------------------------------------------
__device__ __forceinline__ unsigned f2tf32(float x) {
    unsigned r;
    asm("cvt.rna.tf32.f32 %0, %1;" : "=r"(r) : "f"(x));
    return r;
}
__device__ __forceinline__ float tf32f(float x) { return __uint_as_float(f2tf32(x)); }

__device__ __forceinline__ float ex2(float x) {
    float r; asm("ex2.approx.ftz.f32 %0, %1;" : "=f"(r) : "f"(x)); return r;
}

__device__ __forceinline__ void mma_tf32(float* c, const unsigned* a, const unsigned* b) {
    asm volatile(
        "mma.sync.aligned.m16n8k8.row.col.f32.tf32.tf32.f32 "
        "{%0,%1,%2,%3}, {%4,%5,%6,%7}, {%8,%9}, {%0,%1,%2,%3};"
        : "+f"(c[0]), "+f"(c[1]), "+f"(c[2]), "+f"(c[3])
        : "r"(a[0]), "r"(a[1]), "r"(a[2]), "r"(a[3]), "r"(b[0]), "r"(b[1]));
}

__device__ __forceinline__ void cp_async16(void* smem, const void* gmem) {
    unsigned s = (unsigned)__cvta_generic_to_shared(smem);
    asm volatile("cp.async.cg.shared.global [%0], [%1], 16;" :: "r"(s), "l"(gmem));
}
#define CP_COMMIT() asm volatile("cp.async.commit_group;")
#define CP_WAIT1()  asm volatile("cp.async.wait_group 1;")
#define CP_WAIT0()  asm volatile("cp.async.wait_group 0;")

// ---------------------------------------------------------------------------
// convert kernels (all validated in earlier rounds)
// pi32(x) = ((x&7)<<2)|(x>>3) within 32-wide windows  (GEMM A relabel)
// pi64(x) = ((x&7)<<3)|(x>>3) within 64-wide windows  (GEMM B relabel)
// ---------------------------------------------------------------------------
__global__ void cvt_x(const float* __restrict__ in, float* __restrict__ out) {
    size_t base = ((size_t)blockIdx.x * 256 + threadIdx.x) * 4;
    float4 v = *(const float4*)&in[base];
    unsigned low = (unsigned)(base & 31);
    size_t p = (base & ~(size_t)31) + (((low & 7) << 2) | (low >> 3));
    out[p]      = tf32f(v.x);
    out[p + 4]  = tf32f(v.y);
    out[p + 8]  = tf32f(v.z);
    out[p + 12] = tf32f(v.w);
}
__global__ void cvt_w(const float* __restrict__ in, float* __restrict__ out) {
    size_t base = ((size_t)blockIdx.x * 256 + threadIdx.x) * 4;
    float4 v = *(const float4*)&in[base];
    unsigned low = (unsigned)(base & 63);
    size_t p = (base & ~(size_t)63) + (((low & 7) << 3) | (low >> 3));
    out[p]      = tf32f(v.x);
    out[p + 8]  = tf32f(v.y);
    out[p + 16] = tf32f(v.z);
    out[p + 24] = tf32f(v.w);
}

// ---------------------------------------------------------------------------
// TF32 GEMM, fully vectorized fragments, zero in-loop cvt.
// A: gmem pre-permuted pi32+tf32 -> smem [128][32] with XOR chunk swizzle
//    s(r) = ((r&1)<<2)|((r>>1)&3); frags = 8 conflict-free LDS.128/kt.
//    Relabel (R4-validated): A element ks of chunk tg = actual col 8ks+tg,
//    pairing B row ks*8+tg (straight k rows).
// B: gmem pre-permuted pi64+tf32 -> smem [32][128] with R7's swizzle
//    (validated); frags = 4 conflict-free LDS.128 per ks.
// MODE 0: plain [M,1024] fp32   MODE 1: Q head-split tf32
// MODE 2: V head-split tf32 pi64(dh)   MODE 3: K head-split TRANSPOSED tf32
// ---------------------------------------------------------------------------
#define GEMM_SMEM ((2*128*32 + 2*32*128) * 4)   // 65,536 B

template<int MODE>
__global__ __launch_bounds__(256, 2)
void gemm_tf32(const float* __restrict__ X, const float* __restrict__ W,
               const float* __restrict__ bias, float* __restrict__ out,
               float scale)
{
    extern __shared__ float sm[];
    float* As = sm;                       // [2][128][32], XOR-swizzled chunks
    float* Bs = sm + 2*128*32;            // [2][32][128], XOR-swizzled chunks

    const int tid  = threadIdx.x;
    const int lane = tid & 31;
    const int warp = tid >> 5;
    const int g  = lane >> 2;
    const int tg = lane & 3;
    const int m0w = (warp >> 1) * 32;
    const int n0w = (warp & 1) * 64;
    const int row0 = blockIdx.y * 128;
    const int col0 = blockIdx.x * 128;

    // B fragment-read swizzle constants (R7)
    const int sig = (tg & 1) | ((tg & 2) << 1);
    const int pk0 = ((2*g)     ^ sig) << 2;
    const int pk1 = ((2*g + 1) ^ sig) << 2;
    // A fragment-read swizzle constants
    const int sA = ((g & 1) << 2) | (g >> 1);
    const int wA0 = (tg ^ sA) << 2;
    const int wA1 = ((tg ^ sA) ^ 4) << 2;     // chunk tg+4 (= tg^4 for tg<4)

    float c[2][8][4] = {};

    auto load_stage = [&](int kt, int p) {
        float* Ad = As + p*128*32;
        float* Bd = Bs + p*32*128;
        #pragma unroll
        for (int i = 0; i < 4; i++) {
            int idx = tid + i*256;
            int r = idx >> 3, c4 = idx & 7;
            int s = ((r & 1) << 2) | ((r >> 1) & 3);
            cp_async16(&Ad[r*32 + ((c4 ^ s) << 2)],
                       &X[(size_t)(row0 + r)*Dsz + kt*32 + c4*4]);
        }
        #pragma unroll
        for (int i = 0; i < 4; i++) {
            int idx = tid + i*256;
            int r = idx >> 5, c4 = idx & 31;
            int s = (r & 1) | ((r & 2) << 1);
            cp_async16(&Bd[r*128 + ((c4 ^ s) << 2)],
                       &W[(size_t)(kt*32 + r)*Dsz + col0 + c4*4]);
        }
    };

    load_stage(0, 0);
    CP_COMMIT();

    const int NT = Dsz / 32;
    for (int kt = 0; kt < NT; kt++) {
        int p = kt & 1;
        if (kt + 1 < NT) {
            load_stage(kt + 1, p ^ 1);
            CP_COMMIT();
            CP_WAIT1();
        } else {
            CP_WAIT0();
        }
        __syncthreads();

        const float* Ap = As + p*128*32;
        const float* Bp = Bs + p*32*128;

        // A fragments: 8 conflict-free LDS.128 (reused across 4 ks)
        float a4[2][4][4];
        #pragma unroll
        for (int mi = 0; mi < 2; mi++) {
            int r = m0w + mi*16 + g;
            *(float4*)a4[mi][0] = *(const float4*)&Ap[r*32 + wA0];
            *(float4*)a4[mi][1] = *(const float4*)&Ap[(r+8)*32 + wA0];
            *(float4*)a4[mi][2] = *(const float4*)&Ap[r*32 + wA1];
            *(float4*)a4[mi][3] = *(const float4*)&Ap[(r+8)*32 + wA1];
        }

        #pragma unroll
        for (int ks = 0; ks < 4; ks++) {
            // B fragments: 4 conflict-free LDS.128
            float b0[8], b1[8];
            const float* Br0 = &Bp[(ks*8 + tg)*128 + n0w];
            const float* Br1 = &Bp[(ks*8 + tg + 4)*128 + n0w];
            *(float4*)&b0[0] = *(const float4*)&Br0[pk0];
            *(float4*)&b0[4] = *(const float4*)&Br0[pk1];
            *(float4*)&b1[0] = *(const float4*)&Br1[pk0];
            *(float4*)&b1[4] = *(const float4*)&Br1[pk1];

            unsigned a[2][4];
            #pragma unroll
            for (int mi = 0; mi < 2; mi++)
                #pragma unroll
                for (int pp = 0; pp < 4; pp++)
                    a[mi][pp] = __float_as_uint(a4[mi][pp][ks]);

            #pragma unroll
            for (int mi = 0; mi < 2; mi++)
                #pragma unroll
                for (int ni = 0; ni < 8; ni++) {
                    unsigned bf[2] = { __float_as_uint(b0[ni]), __float_as_uint(b1[ni]) };
                    mma_tf32(c[mi][ni], a[mi], bf);
                }
        }
        __syncthreads();
    }

    // epilogue (column mapping identical to R2/R7: ni -> n0w + ni*8 + g)
    #pragma unroll
    for (int mi = 0; mi < 2; mi++) {
        #pragma unroll
        for (int ni = 0; ni < 8; ni++) {
            int cc = col0 + n0w + ni*8 + 2*tg;
            float bx = bias[cc], by = bias[cc+1];
            #pragma unroll
            for (int rr = 0; rr < 2; rr++) {
                int r = row0 + m0w + mi*16 + g + rr*8;
                float vx = (c[mi][ni][rr*2+0] + bx) * scale;
                float vy = (c[mi][ni][rr*2+1] + by) * scale;
                if (MODE == 0) {
                    float2 v = make_float2(vx, vy);
                    *(float2*)&out[(size_t)r * Dsz + cc] = v;
                } else {
                    int b_ = r >> 11, s_ = r & (Ssz-1);
                    int h_ = cc >> 6, dh = cc & (DHs-1);
                    if (MODE == 1) {
                        size_t base = (((size_t)(b_*Hn + h_) * Ssz) + s_) * DHs;
                        float2 v = make_float2(tf32f(vx), tf32f(vy));
                        *(float2*)&out[base + dh] = v;
                    } else if (MODE == 2) {  // V: dh -> pi64(dh)
                        size_t base = (((size_t)(b_*Hn + h_) * Ssz) + s_) * DHs;
                        int p0 = ((dh & 7) << 3) | (dh >> 3);
                        out[base + p0]     = tf32f(vx);
                        out[base + p0 + 8] = tf32f(vy);
                    } else {                  // MODE 3: K transposed [b,h,d,s]
                        size_t kb = (((size_t)(b_*Hn + h_) * DHs) + dh) * Ssz + s_;
                        out[kb]       = tf32f(vx);
                        out[kb + Ssz] = tf32f(vy);
                    }
                }
            }
        }
    }
}

// ---------------------------------------------------------------------------
// Flash attention — R6/R7 compute (measured-good: 257.6 us). Epilogue now
// writes g_o as tf32 + pi32-permuted cols (R4-validated mapping) so the
// final GEMM consumes the vectorized A path.
// ---------------------------------------------------------------------------
#define P68 68
#define ATTN_SMEM ((2*64*64 + 2*64*64 + 128*P68) * 4)   // 100,352 B

__global__ __launch_bounds__(256, 2)
void attn_mma(const float* __restrict__ Q, const float* __restrict__ K,
              const float* __restrict__ V, float* __restrict__ O)
{
    extern __shared__ float sm[];
    float* Kt = sm;                      // [2][64][64]
    float* Vs = sm + 2*64*64;            // [2][64][64]
    float* Ps = sm + 4*64*64;            // [128][68]

    const int tid  = threadIdx.x;
    const int lane = tid & 31;
    const int warp = tid >> 5;
    const int g  = lane >> 2;
    const int tg = lane & 3;
    const int m0w = warp * 16;
    const int r0 = m0w + g;

    const int q0 = blockIdx.x * 128;
    const int h = blockIdx.y, b = blockIdx.z;
    const size_t baseQ = ((size_t)(b*Hn + h)) * Ssz * DHs;
    const float* Qg = Q + baseQ;
    const float* Kg = K + baseQ;
    const float* Vg = V + baseQ;

    const int sig = (tg & 1) | ((tg & 2) << 1);
    const int pk0 = ((2*g)     ^ sig) << 2;
    const int pk1 = ((2*g + 1) ^ sig) << 2;

    float aqf[4][8];
    {
        const float* Qr0 = &Qg[(size_t)(q0 + r0) * DHs];
        const float* Qr1 = &Qg[(size_t)(q0 + r0 + 8) * DHs];
        *(float4*)&aqf[0][0] = *(const float4*)&Qr0[tg*8];
        *(float4*)&aqf[0][4] = *(const float4*)&Qr0[tg*8 + 4];
        *(float4*)&aqf[1][0] = *(const float4*)&Qr1[tg*8];
        *(float4*)&aqf[1][4] = *(const float4*)&Qr1[tg*8 + 4];
        *(float4*)&aqf[2][0] = *(const float4*)&Qr0[(tg+4)*8];
        *(float4*)&aqf[2][4] = *(const float4*)&Qr0[(tg+4)*8 + 4];
        *(float4*)&aqf[3][0] = *(const float4*)&Qr1[(tg+4)*8];
        *(float4*)&aqf[3][4] = *(const float4*)&Qr1[(tg+4)*8 + 4];
    }

    auto load_tile = [&](int t0, int stage) {
        float* Kd = Kt + stage*64*64;
        float* Vd = Vs + stage*64*64;
        #pragma unroll
        for (int i = 0; i < 4; i++) {
            int idx = tid + i*256;
            int r = idx >> 4, c = idx & 15;
            int sk = ((r >> 3) & 1) | (((r >> 3) & 2) << 1);
            cp_async16(&Kd[r*64 + ((c ^ sk) << 2)],
                       &Kg[(size_t)r * Ssz + t0 + (c << 2)]);
            int sv = (r & 1) | ((r & 2) << 1);
            cp_async16(&Vd[r*64 + ((c ^ sv) << 2)],
                       &Vg[(size_t)(t0 + r) * DHs + (c << 2)]);
        }
    };

    load_tile(0, 0);   CP_COMMIT();
    load_tile(64, 1);  CP_COMMIT();

    float o[8][4] = {};
    float m0 = -1e30f, m1 = -1e30f, l0 = 0.0f, l1 = 0.0f;

    const int NTILE = Ssz / 64;   // 32
    for (int t = 0; t < NTILE; t++) {
        if (t + 1 < NTILE) { CP_WAIT1(); } else { CP_WAIT0(); }
        __syncthreads();

        const float* Ktp = Kt + (t & 1)*64*64;
        const float* Vsp = Vs + (t & 1)*64*64;

        float s[8][4] = {};
        #pragma unroll
        for (int ks = 0; ks < 8; ks++) {
            float b0[8], b1[8];
            const float* Kr0 = &Ktp[(tg*8 + ks)*64];
            const float* Kr1 = &Ktp[((tg+4)*8 + ks)*64];
            *(float4*)&b0[0] = *(const float4*)&Kr0[pk0];
            *(float4*)&b0[4] = *(const float4*)&Kr0[pk1];
            *(float4*)&b1[0] = *(const float4*)&Kr1[pk0];
            *(float4*)&b1[4] = *(const float4*)&Kr1[pk1];
            unsigned a[4] = { __float_as_uint(aqf[0][ks]), __float_as_uint(aqf[1][ks]),
                              __float_as_uint(aqf[2][ks]), __float_as_uint(aqf[3][ks]) };
            #pragma unroll
            for (int nt = 0; nt < 8; nt++) {
                unsigned bf[2] = { __float_as_uint(b0[nt]), __float_as_uint(b1[nt]) };
                mma_tf32(s[nt], a, bf);
            }
        }

        float rm0 = -1e30f, rm1 = -1e30f;
        #pragma unroll
        for (int nt = 0; nt < 8; nt++) {
            rm0 = fmaxf(rm0, fmaxf(s[nt][0], s[nt][1]));
            rm1 = fmaxf(rm1, fmaxf(s[nt][2], s[nt][3]));
        }
        rm0 = fmaxf(rm0, __shfl_xor_sync(0xffffffffu, rm0, 1));
        rm0 = fmaxf(rm0, __shfl_xor_sync(0xffffffffu, rm0, 2));
        rm1 = fmaxf(rm1, __shfl_xor_sync(0xffffffffu, rm1, 1));
        rm1 = fmaxf(rm1, __shfl_xor_sync(0xffffffffu, rm1, 2));

        float mn0 = fmaxf(m0, rm0), mn1 = fmaxf(m1, rm1);
        float al0 = ex2(m0 - mn0), al1 = ex2(m1 - mn1);
        m0 = mn0; m1 = mn1;

        float rs0 = 0.0f, rs1 = 0.0f;
        #pragma unroll
        for (int nt = 0; nt < 8; nt++) {
            s[nt][0] = ex2(s[nt][0] - m0);
            s[nt][1] = ex2(s[nt][1] - m0);
            s[nt][2] = ex2(s[nt][2] - m1);
            s[nt][3] = ex2(s[nt][3] - m1);
            rs0 += s[nt][0] + s[nt][1];
            rs1 += s[nt][2] + s[nt][3];
        }
        rs0 += __shfl_xor_sync(0xffffffffu, rs0, 1);
        rs0 += __shfl_xor_sync(0xffffffffu, rs0, 2);
        rs1 += __shfl_xor_sync(0xffffffffu, rs1, 1);
        rs1 += __shfl_xor_sync(0xffffffffu, rs1, 2);

        l0 = l0 * al0 + rs0;
        l1 = l1 * al1 + rs1;
        #pragma unroll
        for (int nt = 0; nt < 8; nt++) {
            o[nt][0] *= al0; o[nt][1] *= al0;
            o[nt][2] *= al1; o[nt][3] *= al1;
        }

        __syncwarp();
        #pragma unroll
        for (int nt = 0; nt < 8; nt++) {
            float2 p01 = make_float2(tf32f(s[nt][0]), tf32f(s[nt][1]));
            float2 p23 = make_float2(tf32f(s[nt][2]), tf32f(s[nt][3]));
            *(float2*)&Ps[r0*P68 + nt*8 + 2*tg]       = p01;
            *(float2*)&Ps[(r0+8)*P68 + nt*8 + 2*tg]   = p23;
        }
        __syncwarp();

        float pa[4][8];
        {
            const float* Pr0 = &Ps[r0*P68];
            const float* Pr1 = &Ps[(r0+8)*P68];
            *(float4*)&pa[0][0] = *(const float4*)&Pr0[tg*8];
            *(float4*)&pa[0][4] = *(const float4*)&Pr0[tg*8 + 4];
            *(float4*)&pa[1][0] = *(const float4*)&Pr1[tg*8];
            *(float4*)&pa[1][4] = *(const float4*)&Pr1[tg*8 + 4];
            *(float4*)&pa[2][0] = *(const float4*)&Pr0[(tg+4)*8];
            *(float4*)&pa[2][4] = *(const float4*)&Pr0[(tg+4)*8 + 4];
            *(float4*)&pa[3][0] = *(const float4*)&Pr1[(tg+4)*8];
            *(float4*)&pa[3][4] = *(const float4*)&Pr1[(tg+4)*8 + 4];
        }
        #pragma unroll
        for (int ks = 0; ks < 8; ks++) {
            float b0[8], b1[8];
            const float* Vr0 = &Vsp[(ks*8 + tg)*64];
            const float* Vr1 = &Vsp[(ks*8 + tg + 4)*64];
            *(float4*)&b0[0] = *(const float4*)&Vr0[pk0];
            *(float4*)&b0[4] = *(const float4*)&Vr0[pk1];
            *(float4*)&b1[0] = *(const float4*)&Vr1[pk0];
            *(float4*)&b1[4] = *(const float4*)&Vr1[pk1];
            unsigned a[4] = { __float_as_uint(pa[0][ks]), __float_as_uint(pa[1][ks]),
                              __float_as_uint(pa[2][ks]), __float_as_uint(pa[3][ks]) };
            #pragma unroll
            for (int nt = 0; nt < 8; nt++) {
                unsigned bf[2] = { __float_as_uint(b0[nt]), __float_as_uint(b1[nt]) };
                mma_tf32(o[nt], a, bf);
            }
        }

        __syncthreads();
        if (t + 2 < NTILE) {
            load_tile((t+2)*64, t & 1);
            CP_COMMIT();
        }
    }

    // ---- normalize + write O: tf32, pi32-permuted cols (R4-validated) ----
    float inv0 = 1.0f / l0, inv1 = 1.0f / l1;
    size_t ob0 = ((size_t)(b*Ssz + q0 + r0)) * Dsz;
    size_t ob1 = ((size_t)(b*Ssz + q0 + r0 + 8)) * Dsz;
    #pragma unroll
    for (int nt = 0; nt < 8; nt++) {
        #pragma unroll
        for (int j = 0; j < 2; j++) {
            int n = nt*8 + 2*tg + j;
            int c = h*DHs + n;
            int pos = (c & ~31) | (((c & 7) << 2) | ((c & 31) >> 3));
            O[ob0 + pos] = tf32f(o[nt][j]   * inv0);
            O[ob1 + pos] = tf32f(o[nt][2+j] * inv1);
        }
    }
}

// ---------------------------------------------------------------------------

extern "C" void kernel_launch(void* const* d_in, const int* in_sizes, int n_in,
                              void* d_out, int out_size)
{
    (void)in_sizes; (void)n_in; (void)out_size;
    const float* queries = (const float*)d_in[0];
    const float* keys    = (const float*)d_in[1];
    const float* values  = (const float*)d_in[2];
    const float* Wq = (const float*)d_in[3];
    const float* bq = (const float*)d_in[4];
    const float* Wk = (const float*)d_in[5];
    const float* bk = (const float*)d_in[6];
    const float* Wv = (const float*)d_in[7];
    const float* bv = (const float*)d_in[8];
    const float* Wo = (const float*)d_in[9];
    const float* bo = (const float*)d_in[10];
    float* out = (float*)d_out;

    void *pxq,*pxk,*pxv,*pwq,*pwk,*pwv,*pwo,*pq,*pk,*pv,*po;
    cudaGetSymbolAddress(&pxq, g_xq); cudaGetSymbolAddress(&pxk, g_xk);
    cudaGetSymbolAddress(&pxv, g_xv);
    cudaGetSymbolAddress(&pwq, g_wq); cudaGetSymbolAddress(&pwk, g_wk);
    cudaGetSymbolAddress(&pwv, g_wv); cudaGetSymbolAddress(&pwo, g_wo);
    cudaGetSymbolAddress(&pq, g_q);   cudaGetSymbolAddress(&pk, g_k);
    cudaGetSymbolAddress(&pv, g_v);   cudaGetSymbolAddress(&po, g_o);

    cudaFuncSetAttribute(gemm_tf32<0>, cudaFuncAttributeMaxDynamicSharedMemorySize, GEMM_SMEM);
    cudaFuncSetAttribute(gemm_tf32<1>, cudaFuncAttributeMaxDynamicSharedMemorySize, GEMM_SMEM);
    cudaFuncSetAttribute(gemm_tf32<2>, cudaFuncAttributeMaxDynamicSharedMemorySize, GEMM_SMEM);
    cudaFuncSetAttribute(gemm_tf32<3>, cudaFuncAttributeMaxDynamicSharedMemorySize, GEMM_SMEM);
    cudaFuncSetAttribute(attn_mma,     cudaFuncAttributeMaxDynamicSharedMemorySize, ATTN_SMEM);

    // converts: inputs (tf32+pi32), weights (tf32+pi64)
    cvt_x<<<Mrows*Dsz/1024, 256>>>(queries, (float*)pxq);
    cvt_x<<<Mrows*Dsz/1024, 256>>>(keys,    (float*)pxk);
    cvt_x<<<Mrows*Dsz/1024, 256>>>(values,  (float*)pxv);
    cvt_w<<<Dsz*Dsz/1024, 256>>>(Wq, (float*)pwq);
    cvt_w<<<Dsz*Dsz/1024, 256>>>(Wk, (float*)pwk);
    cvt_w<<<Dsz*Dsz/1024, 256>>>(Wv, (float*)pwv);
    cvt_w<<<Dsz*Dsz/1024, 256>>>(Wo, (float*)pwo);

    dim3 ggrid(Dsz/128, Mrows/128);   // (8, 32)
    const float qscale = 0.125f * 1.4426950408889634f;   // log2e / sqrt(64)

    gemm_tf32<1><<<ggrid, 256, GEMM_SMEM>>>((const float*)pxq, (const float*)pwq, bq, (float*)pq, qscale);
    gemm_tf32<3><<<ggrid, 256, GEMM_SMEM>>>((const float*)pxk, (const float*)pwk, bk, (float*)pk, 1.0f);
    gemm_tf32<2><<<ggrid, 256, GEMM_SMEM>>>((const float*)pxv, (const float*)pwv, bv, (float*)pv, 1.0f);

    dim3 agrid(Ssz/128, Hn, Bsz);     // (16, 16, 2)
    attn_mma<<<agrid, 256, ATTN_SMEM>>>((const float*)pq, (const float*)pk,
                                        (const float*)pv, (float*)po);

    gemm_tf32<0><<<ggrid, 256, GEMM_SMEM>>>((const float*)po, (const float*)pwo, bo, out, 1.0f);
}

// round 10
// speedup vs baseline: 1.0038x; 1.0038x over previous
#include <cuda_runtime.h>
#include <math.h>

#define Bsz 2
#define Ssz 2048
#define Dsz 1024
#define Hn  16
#define DHs 64
#define Mrows (Bsz*Ssz)

// Scratch (static device globals; no runtime allocation)
__device__ float g_xq[Mrows*Dsz];   // inputs, tf32-rounded + pi32-permuted cols
__device__ float g_xk[Mrows*Dsz];
__device__ float g_xv[Mrows*Dsz];
__device__ float g_wq[Dsz*Dsz];     // weights, tf32-rounded + pi64-permuted cols
__device__ float g_wk[Dsz*Dsz];
__device__ float g_wv[Dsz*Dsz];
__device__ float g_wo[Dsz*Dsz];
__device__ float g_q[Mrows*Dsz];    // [B,H,S,64]  tf32, plain dh
__device__ float g_k[Mrows*Dsz];    // [B,H,64,S]  TRANSPOSED (d-major), tf32
__device__ float g_v[Mrows*Dsz];    // [B,H,S,64]  tf32, dh -> pi64(dh)
__device__ float g_o[Mrows*Dsz];    // [M,1024]    tf32 + pi32-permuted cols

// ---------------------------------------------------------------------------
// helpers
// ---------------------------------------------------------------------------
__device__ __forceinline__ unsigned f2tf32(float x) {
    unsigned r;
    asm("cvt.rna.tf32.f32 %0, %1;" : "=r"(r) : "f"(x));
    return r;
}
__device__ __forceinline__ float tf32f(float x) { return __uint_as_float(f2tf32(x)); }

__device__ __forceinline__ float ex2(float x) {
    float r; asm("ex2.approx.ftz.f32 %0, %1;" : "=f"(r) : "f"(x)); return r;
}

__device__ __forceinline__ void mma_tf32(float* c, const unsigned* a, const unsigned* b) {
    asm volatile(
        "mma.sync.aligned.m16n8k8.row.col.f32.tf32.tf32.f32 "
        "{%0,%1,%2,%3}, {%4,%5,%6,%7}, {%8,%9}, {%0,%1,%2,%3};"
        : "+f"(c[0]), "+f"(c[1]), "+f"(c[2]), "+f"(c[3])
        : "r"(a[0]), "r"(a[1]), "r"(a[2]), "r"(a[3]), "r"(b[0]), "r"(b[1]));
}

__device__ __forceinline__ void cp_async16(void* smem, const void* gmem) {
    unsigned s = (unsigned)__cvta_generic_to_shared(smem);
    asm volatile("cp.async.cg.shared.global [%0], [%1], 16;" :: "r"(s), "l"(gmem));
}
#define CP_COMMIT() asm volatile("cp.async.commit_group;")
#define CP_WAIT1()  asm volatile("cp.async.wait_group 1;")
#define CP_WAIT0()  asm volatile("cp.async.wait_group 0;")

// ---------------------------------------------------------------------------
// convert kernels (all validated in earlier rounds)
// pi32(x) = ((x&7)<<2)|(x>>3) within 32-wide windows  (GEMM A relabel)
// pi64(x) = ((x&7)<<3)|(x>>3) within 64-wide windows  (GEMM B relabel)
// ---------------------------------------------------------------------------
__global__ void cvt_x(const float* __restrict__ in, float* __restrict__ out) {
    size_t base = ((size_t)blockIdx.x * 256 + threadIdx.x) * 4;
    float4 v = *(const float4*)&in[base];
    unsigned low = (unsigned)(base & 31);
    size_t p = (base & ~(size_t)31) + (((low & 7) << 2) | (low >> 3));
    out[p]      = tf32f(v.x);
    out[p + 4]  = tf32f(v.y);
    out[p + 8]  = tf32f(v.z);
    out[p + 12] = tf32f(v.w);
}
__global__ void cvt_w(const float* __restrict__ in, float* __restrict__ out) {
    size_t base = ((size_t)blockIdx.x * 256 + threadIdx.x) * 4;
    float4 v = *(const float4*)&in[base];
    unsigned low = (unsigned)(base & 63);
    size_t p = (base & ~(size_t)63) + (((low & 7) << 3) | (low >> 3));
    out[p]      = tf32f(v.x);
    out[p + 8]  = tf32f(v.y);
    out[p + 16] = tf32f(v.z);
    out[p + 24] = tf32f(v.w);
}

// ---------------------------------------------------------------------------
// TF32 GEMM, fully vectorized fragments, zero in-loop cvt.
// A: gmem pre-permuted pi32+tf32 -> smem [128][32] with XOR chunk swizzle
//    s(r) = ((r&1)<<2)|((r>>1)&3); frags = 8 conflict-free LDS.128/kt.
//    Relabel (R4-validated): A element ks of chunk tg = actual col 8ks+tg,
//    pairing B row ks*8+tg (straight k rows).
// B: gmem pre-permuted pi64+tf32 -> smem [32][128] with R7's swizzle
//    (validated); frags = 4 conflict-free LDS.128 per ks.
// MODE 0: plain [M,1024] fp32   MODE 1: Q head-split tf32
// MODE 2: V head-split tf32 pi64(dh)   MODE 3: K head-split TRANSPOSED tf32
// ---------------------------------------------------------------------------
#define GEMM_SMEM ((2*128*32 + 2*32*128) * 4)   // 65,536 B

template<int MODE>
__global__ __launch_bounds__(256, 2)
void gemm_tf32(const float* __restrict__ X, const float* __restrict__ W,
               const float* __restrict__ bias, float* __restrict__ out,
               float scale)
{
    extern __shared__ float sm[];
    float* As = sm;                       // [2][128][32], XOR-swizzled chunks
    float* Bs = sm + 2*128*32;            // [2][32][128], XOR-swizzled chunks

    const int tid  = threadIdx.x;
    const int lane = tid & 31;
    const int warp = tid >> 5;
    const int g  = lane >> 2;
    const int tg = lane & 3;
    const int m0w = (warp >> 1) * 32;
    const int n0w = (warp & 1) * 64;
    const int row0 = blockIdx.y * 128;
    const int col0 = blockIdx.x * 128;

    // B fragment-read swizzle constants (R7)
    const int sig = (tg & 1) | ((tg & 2) << 1);
    const int pk0 = ((2*g)     ^ sig) << 2;
    const int pk1 = ((2*g + 1) ^ sig) << 2;
    // A fragment-read swizzle constants
    const int sA = ((g & 1) << 2) | (g >> 1);
    const int wA0 = (tg ^ sA) << 2;
    const int wA1 = ((tg ^ sA) ^ 4) << 2;     // chunk tg+4 (= tg^4 for tg<4)

    float c[2][8][4] = {};

    auto load_stage = [&](int kt, int p) {
        float* Ad = As + p*128*32;
        float* Bd = Bs + p*32*128;
        #pragma unroll
        for (int i = 0; i < 4; i++) {
            int idx = tid + i*256;
            int r = idx >> 3, c4 = idx & 7;
            int s = ((r & 1) << 2) | ((r >> 1) & 3);
            cp_async16(&Ad[r*32 + ((c4 ^ s) << 2)],
                       &X[(size_t)(row0 + r)*Dsz + kt*32 + c4*4]);
        }
        #pragma unroll
        for (int i = 0; i < 4; i++) {
            int idx = tid + i*256;
            int r = idx >> 5, c4 = idx & 31;
            int s = (r & 1) | ((r & 2) << 1);
            cp_async16(&Bd[r*128 + ((c4 ^ s) << 2)],
                       &W[(size_t)(kt*32 + r)*Dsz + col0 + c4*4]);
        }
    };

    load_stage(0, 0);
    CP_COMMIT();

    const int NT = Dsz / 32;
    for (int kt = 0; kt < NT; kt++) {
        int p = kt & 1;
        if (kt + 1 < NT) {
            load_stage(kt + 1, p ^ 1);
            CP_COMMIT();
            CP_WAIT1();
        } else {
            CP_WAIT0();
        }
        __syncthreads();

        const float* Ap = As + p*128*32;
        const float* Bp = Bs + p*32*128;

        // A fragments: 8 conflict-free LDS.128 (reused across 4 ks)
        float a4[2][4][4];
        #pragma unroll
        for (int mi = 0; mi < 2; mi++) {
            int r = m0w + mi*16 + g;
            *(float4*)a4[mi][0] = *(const float4*)&Ap[r*32 + wA0];
            *(float4*)a4[mi][1] = *(const float4*)&Ap[(r+8)*32 + wA0];
            *(float4*)a4[mi][2] = *(const float4*)&Ap[r*32 + wA1];
            *(float4*)a4[mi][3] = *(const float4*)&Ap[(r+8)*32 + wA1];
        }

        #pragma unroll
        for (int ks = 0; ks < 4; ks++) {
            // B fragments: 4 conflict-free LDS.128
            float b0[8], b1[8];
            const float* Br0 = &Bp[(ks*8 + tg)*128 + n0w];
            const float* Br1 = &Bp[(ks*8 + tg + 4)*128 + n0w];
            *(float4*)&b0[0] = *(const float4*)&Br0[pk0];
            *(float4*)&b0[4] = *(const float4*)&Br0[pk1];
            *(float4*)&b1[0] = *(const float4*)&Br1[pk0];
            *(float4*)&b1[4] = *(const float4*)&Br1[pk1];

            unsigned a[2][4];
            #pragma unroll
            for (int mi = 0; mi < 2; mi++)
                #pragma unroll
                for (int pp = 0; pp < 4; pp++)
                    a[mi][pp] = __float_as_uint(a4[mi][pp][ks]);

            #pragma unroll
            for (int mi = 0; mi < 2; mi++)
                #pragma unroll
                for (int ni = 0; ni < 8; ni++) {
                    unsigned bf[2] = { __float_as_uint(b0[ni]), __float_as_uint(b1[ni]) };
                    mma_tf32(c[mi][ni], a[mi], bf);
                }
        }
        __syncthreads();
    }

    // epilogue (column mapping identical to R2/R7: ni -> n0w + ni*8 + g)
    #pragma unroll
    for (int mi = 0; mi < 2; mi++) {
        #pragma unroll
        for (int ni = 0; ni < 8; ni++) {
            int cc = col0 + n0w + ni*8 + 2*tg;
            float bx = bias[cc], by = bias[cc+1];
            #pragma unroll
            for (int rr = 0; rr < 2; rr++) {
                int r = row0 + m0w + mi*16 + g + rr*8;
                float vx = (c[mi][ni][rr*2+0] + bx) * scale;
                float vy = (c[mi][ni][rr*2+1] + by) * scale;
                if (MODE == 0) {
                    float2 v = make_float2(vx, vy);
                    *(float2*)&out[(size_t)r * Dsz + cc] = v;
                } else {
                    int b_ = r >> 11, s_ = r & (Ssz-1);
                    int h_ = cc >> 6, dh = cc & (DHs-1);
                    if (MODE == 1) {
                        size_t base = (((size_t)(b_*Hn + h_) * Ssz) + s_) * DHs;
                        float2 v = make_float2(tf32f(vx), tf32f(vy));
                        *(float2*)&out[base + dh] = v;
                    } else if (MODE == 2) {  // V: dh -> pi64(dh)
                        size_t base = (((size_t)(b_*Hn + h_) * Ssz) + s_) * DHs;
                        int p0 = ((dh & 7) << 3) | (dh >> 3);
                        out[base + p0]     = tf32f(vx);
                        out[base + p0 + 8] = tf32f(vy);
                    } else {                  // MODE 3: K transposed [b,h,d,s]
                        size_t kb = (((size_t)(b_*Hn + h_) * DHs) + dh) * Ssz + s_;
                        out[kb]       = tf32f(vx);
                        out[kb + Ssz] = tf32f(vy);
                    }
                }
            }
        }
    }
}

// ---------------------------------------------------------------------------
// Flash attention — R6/R7 compute (measured-good: 257.6 us). Epilogue now
// writes g_o as tf32 + pi32-permuted cols (R4-validated mapping) so the
// final GEMM consumes the vectorized A path.
// ---------------------------------------------------------------------------
#define P68 68
#define ATTN_SMEM ((2*64*64 + 2*64*64 + 128*P68) * 4)   // 100,352 B

__global__ __launch_bounds__(256, 2)
void attn_mma(const float* __restrict__ Q, const float* __restrict__ K,
              const float* __restrict__ V, float* __restrict__ O)
{
    extern __shared__ float sm[];
    float* Kt = sm;                      // [2][64][64]
    float* Vs = sm + 2*64*64;            // [2][64][64]
    float* Ps = sm + 4*64*64;            // [128][68]

    const int tid  = threadIdx.x;
    const int lane = tid & 31;
    const int warp = tid >> 5;
    const int g  = lane >> 2;
    const int tg = lane & 3;
    const int m0w = warp * 16;
    const int r0 = m0w + g;

    const int q0 = blockIdx.x * 128;
    const int h = blockIdx.y, b = blockIdx.z;
    const size_t baseQ = ((size_t)(b*Hn + h)) * Ssz * DHs;
    const float* Qg = Q + baseQ;
    const float* Kg = K + baseQ;
    const float* Vg = V + baseQ;

    const int sig = (tg & 1) | ((tg & 2) << 1);
    const int pk0 = ((2*g)     ^ sig) << 2;
    const int pk1 = ((2*g + 1) ^ sig) << 2;

    float aqf[4][8];
    {
        const float* Qr0 = &Qg[(size_t)(q0 + r0) * DHs];
        const float* Qr1 = &Qg[(size_t)(q0 + r0 + 8) * DHs];
        *(float4*)&aqf[0][0] = *(const float4*)&Qr0[tg*8];
        *(float4*)&aqf[0][4] = *(const float4*)&Qr0[tg*8 + 4];
        *(float4*)&aqf[1][0] = *(const float4*)&Qr1[tg*8];
        *(float4*)&aqf[1][4] = *(const float4*)&Qr1[tg*8 + 4];
        *(float4*)&aqf[2][0] = *(const float4*)&Qr0[(tg+4)*8];
        *(float4*)&aqf[2][4] = *(const float4*)&Qr0[(tg+4)*8 + 4];
        *(float4*)&aqf[3][0] = *(const float4*)&Qr1[(tg+4)*8];
        *(float4*)&aqf[3][4] = *(const float4*)&Qr1[(tg+4)*8 + 4];
    }

    auto load_tile = [&](int t0, int stage) {
        float* Kd = Kt + stage*64*64;
        float* Vd = Vs + stage*64*64;
        #pragma unroll
        for (int i = 0; i < 4; i++) {
            int idx = tid + i*256;
            int r = idx >> 4, c = idx & 15;
            int sk = ((r >> 3) & 1) | (((r >> 3) & 2) << 1);
            cp_async16(&Kd[r*64 + ((c ^ sk) << 2)],
                       &Kg[(size_t)r * Ssz + t0 + (c << 2)]);
            int sv = (r & 1) | ((r & 2) << 1);
            cp_async16(&Vd[r*64 + ((c ^ sv) << 2)],
                       &Vg[(size_t)(t0 + r) * DHs + (c << 2)]);
        }
    };

    load_tile(0, 0);   CP_COMMIT();
    load_tile(64, 1);  CP_COMMIT();

    float o[8][4] = {};
    float m0 = -1e30f, m1 = -1e30f, l0 = 0.0f, l1 = 0.0f;

    const int NTILE = Ssz / 64;   // 32
    for (int t = 0; t < NTILE; t++) {
        if (t + 1 < NTILE) { CP_WAIT1(); } else { CP_WAIT0(); }
        __syncthreads();

        const float* Ktp = Kt + (t & 1)*64*64;
        const float* Vsp = Vs + (t & 1)*64*64;

        float s[8][4] = {};
        #pragma unroll
        for (int ks = 0; ks < 8; ks++) {
            float b0[8], b1[8];
            const float* Kr0 = &Ktp[(tg*8 + ks)*64];
            const float* Kr1 = &Ktp[((tg+4)*8 + ks)*64];
            *(float4*)&b0[0] = *(const float4*)&Kr0[pk0];
            *(float4*)&b0[4] = *(const float4*)&Kr0[pk1];
            *(float4*)&b1[0] = *(const float4*)&Kr1[pk0];
            *(float4*)&b1[4] = *(const float4*)&Kr1[pk1];
            unsigned a[4] = { __float_as_uint(aqf[0][ks]), __float_as_uint(aqf[1][ks]),
                              __float_as_uint(aqf[2][ks]), __float_as_uint(aqf[3][ks]) };
            #pragma unroll
            for (int nt = 0; nt < 8; nt++) {
                unsigned bf[2] = { __float_as_uint(b0[nt]), __float_as_uint(b1[nt]) };
                mma_tf32(s[nt], a, bf);
            }
        }

        float rm0 = -1e30f, rm1 = -1e30f;
        #pragma unroll
        for (int nt = 0; nt < 8; nt++) {
            rm0 = fmaxf(rm0, fmaxf(s[nt][0], s[nt][1]));
            rm1 = fmaxf(rm1, fmaxf(s[nt][2], s[nt][3]));
        }
        rm0 = fmaxf(rm0, __shfl_xor_sync(0xffffffffu, rm0, 1));
        rm0 = fmaxf(rm0, __shfl_xor_sync(0xffffffffu, rm0, 2));
        rm1 = fmaxf(rm1, __shfl_xor_sync(0xffffffffu, rm1, 1));
        rm1 = fmaxf(rm1, __shfl_xor_sync(0xffffffffu, rm1, 2));

        float mn0 = fmaxf(m0, rm0), mn1 = fmaxf(m1, rm1);
        float al0 = ex2(m0 - mn0), al1 = ex2(m1 - mn1);
        m0 = mn0; m1 = mn1;

        float rs0 = 0.0f, rs1 = 0.0f;
        #pragma unroll
        for (int nt = 0; nt < 8; nt++) {
            s[nt][0] = ex2(s[nt][0] - m0);
            s[nt][1] = ex2(s[nt][1] - m0);
            s[nt][2] = ex2(s[nt][2] - m1);
            s[nt][3] = ex2(s[nt][3] - m1);
            rs0 += s[nt][0] + s[nt][1];
            rs1 += s[nt][2] + s[nt][3];
        }
        rs0 += __shfl_xor_sync(0xffffffffu, rs0, 1);
        rs0 += __shfl_xor_sync(0xffffffffu, rs0, 2);
        rs1 += __shfl_xor_sync(0xffffffffu, rs1, 1);
        rs1 += __shfl_xor_sync(0xffffffffu, rs1, 2);

        l0 = l0 * al0 + rs0;
        l1 = l1 * al1 + rs1;
        #pragma unroll
        for (int nt = 0; nt < 8; nt++) {
            o[nt][0] *= al0; o[nt][1] *= al0;
            o[nt][2] *= al1; o[nt][3] *= al1;
        }

        __syncwarp();
        #pragma unroll
        for (int nt = 0; nt < 8; nt++) {
            float2 p01 = make_float2(tf32f(s[nt][0]), tf32f(s[nt][1]));
            float2 p23 = make_float2(tf32f(s[nt][2]), tf32f(s[nt][3]));
            *(float2*)&Ps[r0*P68 + nt*8 + 2*tg]       = p01;
            *(float2*)&Ps[(r0+8)*P68 + nt*8 + 2*tg]   = p23;
        }
        __syncwarp();

        float pa[4][8];
        {
            const float* Pr0 = &Ps[r0*P68];
            const float* Pr1 = &Ps[(r0+8)*P68];
            *(float4*)&pa[0][0] = *(const float4*)&Pr0[tg*8];
            *(float4*)&pa[0][4] = *(const float4*)&Pr0[tg*8 + 4];
            *(float4*)&pa[1][0] = *(const float4*)&Pr1[tg*8];
            *(float4*)&pa[1][4] = *(const float4*)&Pr1[tg*8 + 4];
            *(float4*)&pa[2][0] = *(const float4*)&Pr0[(tg+4)*8];
            *(float4*)&pa[2][4] = *(const float4*)&Pr0[(tg+4)*8 + 4];
            *(float4*)&pa[3][0] = *(const float4*)&Pr1[(tg+4)*8];
            *(float4*)&pa[3][4] = *(const float4*)&Pr1[(tg+4)*8 + 4];
        }
        #pragma unroll
        for (int ks = 0; ks < 8; ks++) {
            float b0[8], b1[8];
            const float* Vr0 = &Vsp[(ks*8 + tg)*64];
            const float* Vr1 = &Vsp[(ks*8 + tg + 4)*64];
            *(float4*)&b0[0] = *(const float4*)&Vr0[pk0];
            *(float4*)&b0[4] = *(const float4*)&Vr0[pk1];
            *(float4*)&b1[0] = *(const float4*)&Vr1[pk0];
            *(float4*)&b1[4] = *(const float4*)&Vr1[pk1];
            unsigned a[4] = { __float_as_uint(pa[0][ks]), __float_as_uint(pa[1][ks]),
                              __float_as_uint(pa[2][ks]), __float_as_uint(pa[3][ks]) };
            #pragma unroll
            for (int nt = 0; nt < 8; nt++) {
                unsigned bf[2] = { __float_as_uint(b0[nt]), __float_as_uint(b1[nt]) };
                mma_tf32(o[nt], a, bf);
            }
        }

        __syncthreads();
        if (t + 2 < NTILE) {
            load_tile((t+2)*64, t & 1);
            CP_COMMIT();
        }
    }

    // ---- normalize + write O: tf32, pi32-permuted cols (R4-validated) ----
    float inv0 = 1.0f / l0, inv1 = 1.0f / l1;
    size_t ob0 = ((size_t)(b*Ssz + q0 + r0)) * Dsz;
    size_t ob1 = ((size_t)(b*Ssz + q0 + r0 + 8)) * Dsz;
    #pragma unroll
    for (int nt = 0; nt < 8; nt++) {
        #pragma unroll
        for (int j = 0; j < 2; j++) {
            int n = nt*8 + 2*tg + j;
            int c = h*DHs + n;
            int pos = (c & ~31) | (((c & 7) << 2) | ((c & 31) >> 3));
            O[ob0 + pos] = tf32f(o[nt][j]   * inv0);
            O[ob1 + pos] = tf32f(o[nt][2+j] * inv1);
        }
    }
}

// ---------------------------------------------------------------------------

extern "C" void kernel_launch(void* const* d_in, const int* in_sizes, int n_in,
                              void* d_out, int out_size)
{
    (void)in_sizes; (void)n_in; (void)out_size;
    const float* queries = (const float*)d_in[0];
    const float* keys    = (const float*)d_in[1];
    const float* values  = (const float*)d_in[2];
    const float* Wq = (const float*)d_in[3];
    const float* bq = (const float*)d_in[4];
    const float* Wk = (const float*)d_in[5];
    const float* bk = (const float*)d_in[6];
    const float* Wv = (const float*)d_in[7];
    const float* bv = (const float*)d_in[8];
    const float* Wo = (const float*)d_in[9];
    const float* bo = (const float*)d_in[10];
    float* out = (float*)d_out;

    void *pxq,*pxk,*pxv,*pwq,*pwk,*pwv,*pwo,*pq,*pk,*pv,*po;
    cudaGetSymbolAddress(&pxq, g_xq); cudaGetSymbolAddress(&pxk, g_xk);
    cudaGetSymbolAddress(&pxv, g_xv);
    cudaGetSymbolAddress(&pwq, g_wq); cudaGetSymbolAddress(&pwk, g_wk);
    cudaGetSymbolAddress(&pwv, g_wv); cudaGetSymbolAddress(&pwo, g_wo);
    cudaGetSymbolAddress(&pq, g_q);   cudaGetSymbolAddress(&pk, g_k);
    cudaGetSymbolAddress(&pv, g_v);   cudaGetSymbolAddress(&po, g_o);

    cudaFuncSetAttribute(gemm_tf32<0>, cudaFuncAttributeMaxDynamicSharedMemorySize, GEMM_SMEM);
    cudaFuncSetAttribute(gemm_tf32<1>, cudaFuncAttributeMaxDynamicSharedMemorySize, GEMM_SMEM);
    cudaFuncSetAttribute(gemm_tf32<2>, cudaFuncAttributeMaxDynamicSharedMemorySize, GEMM_SMEM);
    cudaFuncSetAttribute(gemm_tf32<3>, cudaFuncAttributeMaxDynamicSharedMemorySize, GEMM_SMEM);
    cudaFuncSetAttribute(attn_mma,     cudaFuncAttributeMaxDynamicSharedMemorySize, ATTN_SMEM);

    // converts: inputs (tf32+pi32), weights (tf32+pi64)
    cvt_x<<<Mrows*Dsz/1024, 256>>>(queries, (float*)pxq);
    cvt_x<<<Mrows*Dsz/1024, 256>>>(keys,    (float*)pxk);
    cvt_x<<<Mrows*Dsz/1024, 256>>>(values,  (float*)pxv);
    cvt_w<<<Dsz*Dsz/1024, 256>>>(Wq, (float*)pwq);
    cvt_w<<<Dsz*Dsz/1024, 256>>>(Wk, (float*)pwk);
    cvt_w<<<Dsz*Dsz/1024, 256>>>(Wv, (float*)pwv);
    cvt_w<<<Dsz*Dsz/1024, 256>>>(Wo, (float*)pwo);

    dim3 ggrid(Dsz/128, Mrows/128);   // (8, 32)
    const float qscale = 0.125f * 1.4426950408889634f;   // log2e / sqrt(64)

    gemm_tf32<1><<<ggrid, 256, GEMM_SMEM>>>((const float*)pxq, (const float*)pwq, bq, (float*)pq, qscale);
    gemm_tf32<3><<<ggrid, 256, GEMM_SMEM>>>((const float*)pxk, (const float*)pwk, bk, (float*)pk, 1.0f);
    gemm_tf32<2><<<ggrid, 256, GEMM_SMEM>>>((const float*)pxv, (const float*)pwv, bv, (float*)pv, 1.0f);

    dim3 agrid(Ssz/128, Hn, Bsz);     // (16, 16, 2)
    attn_mma<<<agrid, 256, ATTN_SMEM>>>((const float*)pq, (const float*)pk,
                                        (const float*)pv, (float*)po);

    gemm_tf32<0><<<ggrid, 256, GEMM_SMEM>>>((const float*)po, (const float*)pwo, bo, out, 1.0f);
}

// round 11
// speedup vs baseline: 1.4179x; 1.4125x over previous
#include <cuda_runtime.h>
#include <cuda_fp16.h>
#include <math.h>

#define Bsz 2
#define Ssz 2048
#define Dsz 1024
#define Hn  16
#define DHs 64
#define Mrows (Bsz*Ssz)

// Scratch (static device globals; no runtime allocation)
__device__ unsigned g_wq16[(Dsz/2)*Dsz];  // fp16-packed k-pairs, pi64 n-permute
__device__ unsigned g_wk16[(Dsz/2)*Dsz];
__device__ unsigned g_wv16[(Dsz/2)*Dsz];
__device__ unsigned g_wo16[(Dsz/2)*Dsz];
__device__ float g_q[Mrows*Dsz];    // [B,H,S,64]  tf32-rounded, plain dh
__device__ float g_k[Mrows*Dsz];    // [B,H,64,S]  TRANSPOSED (d-major), tf32-rounded
__device__ float g_v[Mrows*Dsz];    // [B,H,S,64]  tf32-rounded, dh -> pi64(dh)
__device__ float g_o[Mrows*Dsz];    // [M,1024]    fp32 plain

// ---------------------------------------------------------------------------
// helpers
// ---------------------------------------------------------------------------
__device__ __forceinline__ unsigned f2tf32(float x) {
    unsigned r;
    asm("cvt.rna.tf32.f32 %0, %1;" : "=r"(r) : "f"(x));
    return r;
}
__device__ __forceinline__ float tf32f(float x) { return __uint_as_float(f2tf32(x)); }

__device__ __forceinline__ float ex2(float x) {
    float r; asm("ex2.approx.ftz.f32 %0, %1;" : "=f"(r) : "f"(x)); return r;
}

__device__ __forceinline__ unsigned packh2(float lo, float hi) {
    __half2 h = __floats2half2_rn(lo, hi);
    return *reinterpret_cast<unsigned*>(&h);
}

__device__ __forceinline__ void mma_tf32(float* c, const unsigned* a, const unsigned* b) {
    asm volatile(
        "mma.sync.aligned.m16n8k8.row.col.f32.tf32.tf32.f32 "
        "{%0,%1,%2,%3}, {%4,%5,%6,%7}, {%8,%9}, {%0,%1,%2,%3};"
        : "+f"(c[0]), "+f"(c[1]), "+f"(c[2]), "+f"(c[3])
        : "r"(a[0]), "r"(a[1]), "r"(a[2]), "r"(a[3]), "r"(b[0]), "r"(b[1]));
}

__device__ __forceinline__ void mma_f16(float* c, const unsigned* a, const unsigned* b) {
    asm volatile(
        "mma.sync.aligned.m16n8k16.row.col.f32.f16.f16.f32 "
        "{%0,%1,%2,%3}, {%4,%5,%6,%7}, {%8,%9}, {%0,%1,%2,%3};"
        : "+f"(c[0]), "+f"(c[1]), "+f"(c[2]), "+f"(c[3])
        : "r"(a[0]), "r"(a[1]), "r"(a[2]), "r"(a[3]), "r"(b[0]), "r"(b[1]));
}

__device__ __forceinline__ void cp_async16(void* smem, const void* gmem) {
    unsigned s = (unsigned)__cvta_generic_to_shared(smem);
    asm volatile("cp.async.cg.shared.global [%0], [%1], 16;" :: "r"(s), "l"(gmem));
}
#define CP_COMMIT() asm volatile("cp.async.commit_group;")
#define CP_WAIT1()  asm volatile("cp.async.wait_group 1;")
#define CP_WAIT0()  asm volatile("cp.async.wait_group 0;")

// ---------------------------------------------------------------------------
// Weight convert: fp16 pack of k-pairs + pi64 n-permute within 64-windows.
// out word [kk][(n&~63) + pi64(n&63)] = half2( W[2kk][n], W[2kk+1][n] )
// pi64(x) = ((x&7)<<3)|(x>>3) (involution; stored col x holds actual n=pi64(x))
// ---------------------------------------------------------------------------
__global__ void cvt_w16(const float* __restrict__ in, unsigned* __restrict__ out) {
    int gid = blockIdx.x * 256 + threadIdx.x;     // 131072 threads
    int kk = gid >> 8;                            // [0,512)
    int n  = (gid & 255) * 4;                     // [0,1024) step 4
    float4 v0 = *(const float4*)&in[(size_t)(2*kk)     * Dsz + n];
    float4 v1 = *(const float4*)&in[(size_t)(2*kk + 1) * Dsz + n];
    float a0[4] = {v0.x, v0.y, v0.z, v0.w};
    float a1[4] = {v1.x, v1.y, v1.z, v1.w};
    size_t base = (size_t)kk * Dsz + (n & ~63);
    #pragma unroll
    for (int i = 0; i < 4; i++) {
        int x = (n & 63) + i;
        int p = ((x & 7) << 3) | (x >> 3);
        out[base + p] = packh2(a0[i], a1[i]);
    }
}

// ---------------------------------------------------------------------------
// FP16 GEMM: out = X[M,1024] @ W + bias. 128x128 tile, BK=32, m16n8k16.
// A: fp32 smem (cp.async, pitch 40 -> conflict-free LDS.64), packed to half2
//    at fragment time: 16 LDS.64 + 16 packs per kt.
// B: pre-packed/permuted fp16 words, smem [16][128] with XOR chunk swizzle
//    s(r)=((r&1)<<2)|((r>>1)&1) -> 8 conflict-free LDS.128 per kt, zero cvt.
//    Logical word 8g+j in 64-window = actual col j*8+g -> ni=j: epilogue
//    column mapping IDENTICAL to R7.
// MODE 0: plain fp32; 1: Q head-split tf32; 2: V head-split tf32 pi64(dh);
// MODE 3: K head-split TRANSPOSED tf32.
// ---------------------------------------------------------------------------
#define A_PITCH 40
#define GEMM_SMEM ((2*128*A_PITCH + 2*16*128) * 4)   // 57,344 B

template<int MODE>
__global__ __launch_bounds__(256, 2)
void gemm_f16(const float* __restrict__ X, const unsigned* __restrict__ Wh,
              const float* __restrict__ bias, float* __restrict__ out,
              float scale)
{
    extern __shared__ float sm[];
    float* As = sm;                                   // [2][128][40] fp32
    unsigned* Bs = (unsigned*)(sm + 2*128*A_PITCH);   // [2][16][128] half2 words

    const int tid  = threadIdx.x;
    const int lane = tid & 31;
    const int warp = tid >> 5;
    const int g  = lane >> 2;
    const int tg = lane & 3;
    const int m0w = (warp >> 1) * 32;
    const int n0w = (warp & 1) * 64;
    const int row0 = blockIdx.y * 128;
    const int col0 = blockIdx.x * 128;

    const int sB = ((tg & 1) << 2) | ((tg >> 1) & 1);   // B frag-row swizzle class
    const int cb = (n0w >> 2) + 2*g;                    // logical base chunk

    float c[2][8][4] = {};

    auto load_stage = [&](int kt, int p) {
        float* Ad = As + p*128*A_PITCH;
        unsigned* Bd = Bs + p*16*128;
        #pragma unroll
        for (int i = 0; i < 4; i++) {
            int idx = tid + i*256;
            int r = idx >> 3, c4 = idx & 7;
            cp_async16(&Ad[r*A_PITCH + c4*4], &X[(size_t)(row0 + r)*Dsz + kt*32 + c4*4]);
        }
        #pragma unroll
        for (int i = 0; i < 2; i++) {
            int idx = tid + i*256;
            int r = idx >> 5, cc = idx & 31;
            int s = ((r & 1) << 2) | ((r >> 1) & 1);
            cp_async16(&Bd[r*128 + ((cc ^ s) << 2)],
                       &Wh[(size_t)(kt*16 + r)*Dsz + col0 + (cc << 2)]);
        }
    };

    load_stage(0, 0);
    CP_COMMIT();

    const int NT = Dsz / 32;   // 32
    for (int kt = 0; kt < NT; kt++) {
        int p = kt & 1;
        if (kt + 1 < NT) {
            load_stage(kt + 1, p ^ 1);
            CP_COMMIT();
            CP_WAIT1();
        } else {
            CP_WAIT0();
        }
        __syncthreads();

        const float* Ap = As + p*128*A_PITCH;
        const unsigned* Bp = Bs + p*16*128;

        #pragma unroll
        for (int ks = 0; ks < 2; ks++) {
            // B fragments: 4 conflict-free LDS.128
            unsigned bw0[8], bw1[8];
            {
                const unsigned* Br0 = &Bp[(8*ks + tg) * 128];
                const unsigned* Br1 = &Bp[(8*ks + tg + 4) * 128];
                *(uint4*)&bw0[0] = *(const uint4*)&Br0[((cb)     ^ sB) << 2];
                *(uint4*)&bw0[4] = *(const uint4*)&Br0[((cb + 1) ^ sB) << 2];
                *(uint4*)&bw1[0] = *(const uint4*)&Br1[((cb)     ^ sB) << 2];
                *(uint4*)&bw1[4] = *(const uint4*)&Br1[((cb + 1) ^ sB) << 2];
            }
            // A fragments: 8 conflict-free LDS.64 + 8 half2 packs
            unsigned af[2][4];
            #pragma unroll
            for (int mi = 0; mi < 2; mi++) {
                int r = m0w + mi*16 + g;
                int kc = 16*ks + 2*tg;
                float2 p00 = *(const float2*)&Ap[r*A_PITCH + kc];
                float2 p01 = *(const float2*)&Ap[(r+8)*A_PITCH + kc];
                float2 p10 = *(const float2*)&Ap[r*A_PITCH + kc + 8];
                float2 p11 = *(const float2*)&Ap[(r+8)*A_PITCH + kc + 8];
                af[mi][0] = packh2(p00.x, p00.y);
                af[mi][1] = packh2(p01.x, p01.y);
                af[mi][2] = packh2(p10.x, p10.y);
                af[mi][3] = packh2(p11.x, p11.y);
            }
            #pragma unroll
            for (int mi = 0; mi < 2; mi++)
                #pragma unroll
                for (int ni = 0; ni < 8; ni++) {
                    unsigned bf[2] = { bw0[ni], bw1[ni] };
                    mma_f16(c[mi][ni], af[mi], bf);
                }
        }
        __syncthreads();
    }

    // epilogue (column mapping identical to R7: ni -> n0w + ni*8 + g)
    #pragma unroll
    for (int mi = 0; mi < 2; mi++) {
        #pragma unroll
        for (int ni = 0; ni < 8; ni++) {
            int cc = col0 + n0w + ni*8 + 2*tg;
            float bx = bias[cc], by = bias[cc+1];
            #pragma unroll
            for (int rr = 0; rr < 2; rr++) {
                int r = row0 + m0w + mi*16 + g + rr*8;
                float vx = (c[mi][ni][rr*2+0] + bx) * scale;
                float vy = (c[mi][ni][rr*2+1] + by) * scale;
                if (MODE == 0) {
                    float2 v = make_float2(vx, vy);
                    *(float2*)&out[(size_t)r * Dsz + cc] = v;
                } else {
                    int b_ = r >> 11, s_ = r & (Ssz-1);
                    int h_ = cc >> 6, dh = cc & (DHs-1);
                    if (MODE == 1) {
                        size_t base = (((size_t)(b_*Hn + h_) * Ssz) + s_) * DHs;
                        float2 v = make_float2(tf32f(vx), tf32f(vy));
                        *(float2*)&out[base + dh] = v;
                    } else if (MODE == 2) {  // V: dh -> pi64(dh)
                        size_t base = (((size_t)(b_*Hn + h_) * Ssz) + s_) * DHs;
                        int p0 = ((dh & 7) << 3) | (dh >> 3);
                        out[base + p0]     = tf32f(vx);
                        out[base + p0 + 8] = tf32f(vy);
                    } else {                  // MODE 3: K transposed [b,h,d,s]
                        size_t kb = (((size_t)(b_*Hn + h_) * DHs) + dh) * Ssz + s_;
                        out[kb]       = tf32f(vx);
                        out[kb + Ssz] = tf32f(vy);
                    }
                }
            }
        }
    }
}

// ---------------------------------------------------------------------------
// Flash attention — BYTE-IDENTICAL compute to R6/R7 (measured: 257.6 us),
// plain [B,S,D] fp32 output epilogue (R7 version).
// ---------------------------------------------------------------------------
#define P68 68
#define ATTN_SMEM ((2*64*64 + 2*64*64 + 128*P68) * 4)   // 100,352 B

__global__ __launch_bounds__(256, 2)
void attn_mma(const float* __restrict__ Q, const float* __restrict__ K,
              const float* __restrict__ V, float* __restrict__ O)
{
    extern __shared__ float sm[];
    float* Kt = sm;                      // [2][64][64]
    float* Vs = sm + 2*64*64;            // [2][64][64]
    float* Ps = sm + 4*64*64;            // [128][68]

    const int tid  = threadIdx.x;
    const int lane = tid & 31;
    const int warp = tid >> 5;
    const int g  = lane >> 2;
    const int tg = lane & 3;
    const int m0w = warp * 16;
    const int r0 = m0w + g;

    const int q0 = blockIdx.x * 128;
    const int h = blockIdx.y, b = blockIdx.z;
    const size_t baseQ = ((size_t)(b*Hn + h)) * Ssz * DHs;
    const float* Qg = Q + baseQ;
    const float* Kg = K + baseQ;
    const float* Vg = V + baseQ;

    const int sig = (tg & 1) | ((tg & 2) << 1);
    const int pk0 = ((2*g)     ^ sig) << 2;
    const int pk1 = ((2*g + 1) ^ sig) << 2;

    float aqf[4][8];
    {
        const float* Qr0 = &Qg[(size_t)(q0 + r0) * DHs];
        const float* Qr1 = &Qg[(size_t)(q0 + r0 + 8) * DHs];
        *(float4*)&aqf[0][0] = *(const float4*)&Qr0[tg*8];
        *(float4*)&aqf[0][4] = *(const float4*)&Qr0[tg*8 + 4];
        *(float4*)&aqf[1][0] = *(const float4*)&Qr1[tg*8];
        *(float4*)&aqf[1][4] = *(const float4*)&Qr1[tg*8 + 4];
        *(float4*)&aqf[2][0] = *(const float4*)&Qr0[(tg+4)*8];
        *(float4*)&aqf[2][4] = *(const float4*)&Qr0[(tg+4)*8 + 4];
        *(float4*)&aqf[3][0] = *(const float4*)&Qr1[(tg+4)*8];
        *(float4*)&aqf[3][4] = *(const float4*)&Qr1[(tg+4)*8 + 4];
    }

    auto load_tile = [&](int t0, int stage) {
        float* Kd = Kt + stage*64*64;
        float* Vd = Vs + stage*64*64;
        #pragma unroll
        for (int i = 0; i < 4; i++) {
            int idx = tid + i*256;
            int r = idx >> 4, c = idx & 15;
            int sk = ((r >> 3) & 1) | (((r >> 3) & 2) << 1);
            cp_async16(&Kd[r*64 + ((c ^ sk) << 2)],
                       &Kg[(size_t)r * Ssz + t0 + (c << 2)]);
            int sv = (r & 1) | ((r & 2) << 1);
            cp_async16(&Vd[r*64 + ((c ^ sv) << 2)],
                       &Vg[(size_t)(t0 + r) * DHs + (c << 2)]);
        }
    };

    load_tile(0, 0);   CP_COMMIT();
    load_tile(64, 1);  CP_COMMIT();

    float o[8][4] = {};
    float m0 = -1e30f, m1 = -1e30f, l0 = 0.0f, l1 = 0.0f;

    const int NTILE = Ssz / 64;   // 32
    for (int t = 0; t < NTILE; t++) {
        if (t + 1 < NTILE) { CP_WAIT1(); } else { CP_WAIT0(); }
        __syncthreads();

        const float* Ktp = Kt + (t & 1)*64*64;
        const float* Vsp = Vs + (t & 1)*64*64;

        float s[8][4] = {};
        #pragma unroll
        for (int ks = 0; ks < 8; ks++) {
            float b0[8], b1[8];
            const float* Kr0 = &Ktp[(tg*8 + ks)*64];
            const float* Kr1 = &Ktp[((tg+4)*8 + ks)*64];
            *(float4*)&b0[0] = *(const float4*)&Kr0[pk0];
            *(float4*)&b0[4] = *(const float4*)&Kr0[pk1];
            *(float4*)&b1[0] = *(const float4*)&Kr1[pk0];
            *(float4*)&b1[4] = *(const float4*)&Kr1[pk1];
            unsigned a[4] = { __float_as_uint(aqf[0][ks]), __float_as_uint(aqf[1][ks]),
                              __float_as_uint(aqf[2][ks]), __float_as_uint(aqf[3][ks]) };
            #pragma unroll
            for (int nt = 0; nt < 8; nt++) {
                unsigned bf[2] = { __float_as_uint(b0[nt]), __float_as_uint(b1[nt]) };
                mma_tf32(s[nt], a, bf);
            }
        }

        float rm0 = -1e30f, rm1 = -1e30f;
        #pragma unroll
        for (int nt = 0; nt < 8; nt++) {
            rm0 = fmaxf(rm0, fmaxf(s[nt][0], s[nt][1]));
            rm1 = fmaxf(rm1, fmaxf(s[nt][2], s[nt][3]));
        }
        rm0 = fmaxf(rm0, __shfl_xor_sync(0xffffffffu, rm0, 1));
        rm0 = fmaxf(rm0, __shfl_xor_sync(0xffffffffu, rm0, 2));
        rm1 = fmaxf(rm1, __shfl_xor_sync(0xffffffffu, rm1, 1));
        rm1 = fmaxf(rm1, __shfl_xor_sync(0xffffffffu, rm1, 2));

        float mn0 = fmaxf(m0, rm0), mn1 = fmaxf(m1, rm1);
        float al0 = ex2(m0 - mn0), al1 = ex2(m1 - mn1);
        m0 = mn0; m1 = mn1;

        float rs0 = 0.0f, rs1 = 0.0f;
        #pragma unroll
        for (int nt = 0; nt < 8; nt++) {
            s[nt][0] = ex2(s[nt][0] - m0);
            s[nt][1] = ex2(s[nt][1] - m0);
            s[nt][2] = ex2(s[nt][2] - m1);
            s[nt][3] = ex2(s[nt][3] - m1);
            rs0 += s[nt][0] + s[nt][1];
            rs1 += s[nt][2] + s[nt][3];
        }
        rs0 += __shfl_xor_sync(0xffffffffu, rs0, 1);
        rs0 += __shfl_xor_sync(0xffffffffu, rs0, 2);
        rs1 += __shfl_xor_sync(0xffffffffu, rs1, 1);
        rs1 += __shfl_xor_sync(0xffffffffu, rs1, 2);

        l0 = l0 * al0 + rs0;
        l1 = l1 * al1 + rs1;
        #pragma unroll
        for (int nt = 0; nt < 8; nt++) {
            o[nt][0] *= al0; o[nt][1] *= al0;
            o[nt][2] *= al1; o[nt][3] *= al1;
        }

        __syncwarp();
        #pragma unroll
        for (int nt = 0; nt < 8; nt++) {
            float2 p01 = make_float2(tf32f(s[nt][0]), tf32f(s[nt][1]));
            float2 p23 = make_float2(tf32f(s[nt][2]), tf32f(s[nt][3]));
            *(float2*)&Ps[r0*P68 + nt*8 + 2*tg]       = p01;
            *(float2*)&Ps[(r0+8)*P68 + nt*8 + 2*tg]   = p23;
        }
        __syncwarp();

        float pa[4][8];
        {
            const float* Pr0 = &Ps[r0*P68];
            const float* Pr1 = &Ps[(r0+8)*P68];
            *(float4*)&pa[0][0] = *(const float4*)&Pr0[tg*8];
            *(float4*)&pa[0][4] = *(const float4*)&Pr0[tg*8 + 4];
            *(float4*)&pa[1][0] = *(const float4*)&Pr1[tg*8];
            *(float4*)&pa[1][4] = *(const float4*)&Pr1[tg*8 + 4];
            *(float4*)&pa[2][0] = *(const float4*)&Pr0[(tg+4)*8];
            *(float4*)&pa[2][4] = *(const float4*)&Pr0[(tg+4)*8 + 4];
            *(float4*)&pa[3][0] = *(const float4*)&Pr1[(tg+4)*8];
            *(float4*)&pa[3][4] = *(const float4*)&Pr1[(tg+4)*8 + 4];
        }
        #pragma unroll
        for (int ks = 0; ks < 8; ks++) {
            float b0[8], b1[8];
            const float* Vr0 = &Vsp[(ks*8 + tg)*64];
            const float* Vr1 = &Vsp[(ks*8 + tg + 4)*64];
            *(float4*)&b0[0] = *(const float4*)&Vr0[pk0];
            *(float4*)&b0[4] = *(const float4*)&Vr0[pk1];
            *(float4*)&b1[0] = *(const float4*)&Vr1[pk0];
            *(float4*)&b1[4] = *(const float4*)&Vr1[pk1];
            unsigned a[4] = { __float_as_uint(pa[0][ks]), __float_as_uint(pa[1][ks]),
                              __float_as_uint(pa[2][ks]), __float_as_uint(pa[3][ks]) };
            #pragma unroll
            for (int nt = 0; nt < 8; nt++) {
                unsigned bf[2] = { __float_as_uint(b0[nt]), __float_as_uint(b1[nt]) };
                mma_tf32(o[nt], a, bf);
            }
        }

        __syncthreads();
        if (t + 2 < NTILE) {
            load_tile((t+2)*64, t & 1);
            CP_COMMIT();
        }
    }

    float inv0 = 1.0f / l0, inv1 = 1.0f / l1;
    size_t ob0 = ((size_t)(b*Ssz + q0 + r0)) * Dsz + h*DHs;
    size_t ob1 = ((size_t)(b*Ssz + q0 + r0 + 8)) * Dsz + h*DHs;
    #pragma unroll
    for (int nt = 0; nt < 8; nt++) {
        int n = nt*8 + 2*tg;
        float2 va = make_float2(o[nt][0]*inv0, o[nt][1]*inv0);
        float2 vb = make_float2(o[nt][2]*inv1, o[nt][3]*inv1);
        *(float2*)&O[ob0 + n] = va;
        *(float2*)&O[ob1 + n] = vb;
    }
}

// ---------------------------------------------------------------------------

extern "C" void kernel_launch(void* const* d_in, const int* in_sizes, int n_in,
                              void* d_out, int out_size)
{
    (void)in_sizes; (void)n_in; (void)out_size;
    const float* queries = (const float*)d_in[0];
    const float* keys    = (const float*)d_in[1];
    const float* values  = (const float*)d_in[2];
    const float* Wq = (const float*)d_in[3];
    const float* bq = (const float*)d_in[4];
    const float* Wk = (const float*)d_in[5];
    const float* bk = (const float*)d_in[6];
    const float* Wv = (const float*)d_in[7];
    const float* bv = (const float*)d_in[8];
    const float* Wo = (const float*)d_in[9];
    const float* bo = (const float*)d_in[10];
    float* out = (float*)d_out;

    void *pwq,*pwk,*pwv,*pwo,*pq,*pk,*pv,*po;
    cudaGetSymbolAddress(&pwq, g_wq16); cudaGetSymbolAddress(&pwk, g_wk16);
    cudaGetSymbolAddress(&pwv, g_wv16); cudaGetSymbolAddress(&pwo, g_wo16);
    cudaGetSymbolAddress(&pq, g_q);     cudaGetSymbolAddress(&pk, g_k);
    cudaGetSymbolAddress(&pv, g_v);     cudaGetSymbolAddress(&po, g_o);

    cudaFuncSetAttribute(gemm_f16<0>, cudaFuncAttributeMaxDynamicSharedMemorySize, GEMM_SMEM);
    cudaFuncSetAttribute(gemm_f16<1>, cudaFuncAttributeMaxDynamicSharedMemorySize, GEMM_SMEM);
    cudaFuncSetAttribute(gemm_f16<2>, cudaFuncAttributeMaxDynamicSharedMemorySize, GEMM_SMEM);
    cudaFuncSetAttribute(gemm_f16<3>, cudaFuncAttributeMaxDynamicSharedMemorySize, GEMM_SMEM);
    cudaFuncSetAttribute(attn_mma,    cudaFuncAttributeMaxDynamicSharedMemorySize, ATTN_SMEM);

    // weight converts: fp16 k-pair pack + pi64 n-permute (4 MB -> 2 MB each)
    cvt_w16<<<512, 256>>>(Wq, (unsigned*)pwq);
    cvt_w16<<<512, 256>>>(Wk, (unsigned*)pwk);
    cvt_w16<<<512, 256>>>(Wv, (unsigned*)pwv);
    cvt_w16<<<512, 256>>>(Wo, (unsigned*)pwo);

    dim3 ggrid(Dsz/128, Mrows/128);   // (8, 32)
    const float qscale = 0.125f * 1.4426950408889634f;   // log2e / sqrt(64)

    gemm_f16<1><<<ggrid, 256, GEMM_SMEM>>>(queries, (const unsigned*)pwq, bq, (float*)pq, qscale);
    gemm_f16<3><<<ggrid, 256, GEMM_SMEM>>>(keys,    (const unsigned*)pwk, bk, (float*)pk, 1.0f);
    gemm_f16<2><<<ggrid, 256, GEMM_SMEM>>>(values,  (const unsigned*)pwv, bv, (float*)pv, 1.0f);

    dim3 agrid(Ssz/128, Hn, Bsz);     // (16, 16, 2)
    attn_mma<<<agrid, 256, ATTN_SMEM>>>((const float*)pq, (const float*)pk,
                                        (const float*)pv, (float*)po);

    gemm_f16<0><<<ggrid, 256, GEMM_SMEM>>>((const float*)po, (const unsigned*)pwo, bo, out, 1.0f);
}

// round 12
// speedup vs baseline: 2.0853x; 1.4706x over previous
#include <cuda_runtime.h>
#include <cuda_fp16.h>
#include <math.h>

#define Bsz 2
#define Ssz 2048
#define Dsz 1024
#define Hn  16
#define DHs 64
#define Mrows (Bsz*Ssz)

// Scratch (static device globals; no runtime allocation)
__device__ unsigned g_wq16[(Dsz/2)*Dsz];  // fp16-packed k-pairs, pi64 n-permute
__device__ unsigned g_wk16[(Dsz/2)*Dsz];
__device__ unsigned g_wv16[(Dsz/2)*Dsz];
__device__ unsigned g_wo16[(Dsz/2)*Dsz];
__device__ float    g_q[Mrows*Dsz];        // [B,H,S,64] fp32, plain dh
__device__ unsigned g_k16[Mrows*Dsz/2];    // [B,H,32(dd),S]: (K[2dd][s],K[2dd+1][s])
__device__ unsigned g_v16[Mrows*Dsz/2];    // [B,H,S/2(w),64]: kv-pair (kappa,kappa+8) x pi64(dh)
__device__ float    g_o[Mrows*Dsz];        // [M,1024] fp32 plain

// ---------------------------------------------------------------------------
// helpers
// ---------------------------------------------------------------------------
__device__ __forceinline__ float ex2(float x) {
    float r; asm("ex2.approx.ftz.f32 %0, %1;" : "=f"(r) : "f"(x)); return r;
}
__device__ __forceinline__ unsigned packh2(float lo, float hi) {
    __half2 h = __floats2half2_rn(lo, hi);
    return *reinterpret_cast<unsigned*>(&h);
}
__device__ __forceinline__ void mma_f16(float* c, const unsigned* a, const unsigned* b) {
    asm volatile(
        "mma.sync.aligned.m16n8k16.row.col.f32.f16.f16.f32 "
        "{%0,%1,%2,%3}, {%4,%5,%6,%7}, {%8,%9}, {%0,%1,%2,%3};"
        : "+f"(c[0]), "+f"(c[1]), "+f"(c[2]), "+f"(c[3])
        : "r"(a[0]), "r"(a[1]), "r"(a[2]), "r"(a[3]), "r"(b[0]), "r"(b[1]));
}
__device__ __forceinline__ void cp_async16(void* smem, const void* gmem) {
    unsigned s = (unsigned)__cvta_generic_to_shared(smem);
    asm volatile("cp.async.cg.shared.global [%0], [%1], 16;" :: "r"(s), "l"(gmem));
}
#define CP_COMMIT() asm volatile("cp.async.commit_group;")
#define CP_WAIT1()  asm volatile("cp.async.wait_group 1;")
#define CP_WAIT0()  asm volatile("cp.async.wait_group 0;")

// ---------------------------------------------------------------------------
// Weight convert (R11, validated): fp16 pack of k-pairs + pi64 n-permute.
// ---------------------------------------------------------------------------
__global__ void cvt_w16(const float* __restrict__ in, unsigned* __restrict__ out) {
    int gid = blockIdx.x * 256 + threadIdx.x;
    int kk = gid >> 8;
    int n  = (gid & 255) * 4;
    float4 v0 = *(const float4*)&in[(size_t)(2*kk)     * Dsz + n];
    float4 v1 = *(const float4*)&in[(size_t)(2*kk + 1) * Dsz + n];
    float a0[4] = {v0.x, v0.y, v0.z, v0.w};
    float a1[4] = {v1.x, v1.y, v1.z, v1.w};
    size_t base = (size_t)kk * Dsz + (n & ~63);
    #pragma unroll
    for (int i = 0; i < 4; i++) {
        int x = (n & 63) + i;
        int p = ((x & 7) << 3) | (x >> 3);
        out[base + p] = packh2(a0[i], a1[i]);
    }
}

// ---------------------------------------------------------------------------
// FP16 GEMM (R11 main loop, validated). Epilogue modes:
// MODE 0: plain [M,1024] fp32
// MODE 1: Q head-split [B,H,S,64] fp32
// MODE 2: V -> g_v16: word(w, pi64(dh)) = half2(V[kappa][dh], V[kappa+8][dh]),
//         w = 8*((s&63)>>4) + (s&7)  (the C-fragment rr=0/1 rows ARE the pair)
// MODE 3: K -> g_k16: word(dd, s) = half2(K[2dd][s], K[2dd+1][s])
//         (cc, cc+1 of the epilogue ARE the d pair)
// ---------------------------------------------------------------------------
#define A_PITCH 40
#define GEMM_SMEM ((2*128*A_PITCH + 2*16*128) * 4)   // 57,344 B

template<int MODE>
__global__ __launch_bounds__(256, 2)
void gemm_f16(const float* __restrict__ X, const unsigned* __restrict__ Wh,
              const float* __restrict__ bias, void* __restrict__ outv,
              float scale)
{
    extern __shared__ float sm[];
    float* As = sm;                                   // [2][128][40] fp32
    unsigned* Bs = (unsigned*)(sm + 2*128*A_PITCH);   // [2][16][128] half2 words

    const int tid  = threadIdx.x;
    const int lane = tid & 31;
    const int warp = tid >> 5;
    const int g  = lane >> 2;
    const int tg = lane & 3;
    const int m0w = (warp >> 1) * 32;
    const int n0w = (warp & 1) * 64;
    const int row0 = blockIdx.y * 128;
    const int col0 = blockIdx.x * 128;

    const int sB = ((tg & 1) << 2) | ((tg >> 1) & 1);
    const int cb = (n0w >> 2) + 2*g;

    float c[2][8][4] = {};

    auto load_stage = [&](int kt, int p) {
        float* Ad = As + p*128*A_PITCH;
        unsigned* Bd = Bs + p*16*128;
        #pragma unroll
        for (int i = 0; i < 4; i++) {
            int idx = tid + i*256;
            int r = idx >> 3, c4 = idx & 7;
            cp_async16(&Ad[r*A_PITCH + c4*4], &X[(size_t)(row0 + r)*Dsz + kt*32 + c4*4]);
        }
        #pragma unroll
        for (int i = 0; i < 2; i++) {
            int idx = tid + i*256;
            int r = idx >> 5, cc = idx & 31;
            int s = ((r & 1) << 2) | ((r >> 1) & 1);
            cp_async16(&Bd[r*128 + ((cc ^ s) << 2)],
                       &Wh[(size_t)(kt*16 + r)*Dsz + col0 + (cc << 2)]);
        }
    };

    load_stage(0, 0);
    CP_COMMIT();

    const int NT = Dsz / 32;
    for (int kt = 0; kt < NT; kt++) {
        int p = kt & 1;
        if (kt + 1 < NT) {
            load_stage(kt + 1, p ^ 1);
            CP_COMMIT();
            CP_WAIT1();
        } else {
            CP_WAIT0();
        }
        __syncthreads();

        const float* Ap = As + p*128*A_PITCH;
        const unsigned* Bp = Bs + p*16*128;

        #pragma unroll
        for (int ks = 0; ks < 2; ks++) {
            unsigned bw0[8], bw1[8];
            {
                const unsigned* Br0 = &Bp[(8*ks + tg) * 128];
                const unsigned* Br1 = &Bp[(8*ks + tg + 4) * 128];
                *(uint4*)&bw0[0] = *(const uint4*)&Br0[((cb)     ^ sB) << 2];
                *(uint4*)&bw0[4] = *(const uint4*)&Br0[((cb + 1) ^ sB) << 2];
                *(uint4*)&bw1[0] = *(const uint4*)&Br1[((cb)     ^ sB) << 2];
                *(uint4*)&bw1[4] = *(const uint4*)&Br1[((cb + 1) ^ sB) << 2];
            }
            unsigned af[2][4];
            #pragma unroll
            for (int mi = 0; mi < 2; mi++) {
                int r = m0w + mi*16 + g;
                int kc = 16*ks + 2*tg;
                float2 p00 = *(const float2*)&Ap[r*A_PITCH + kc];
                float2 p01 = *(const float2*)&Ap[(r+8)*A_PITCH + kc];
                float2 p10 = *(const float2*)&Ap[r*A_PITCH + kc + 8];
                float2 p11 = *(const float2*)&Ap[(r+8)*A_PITCH + kc + 8];
                af[mi][0] = packh2(p00.x, p00.y);
                af[mi][1] = packh2(p01.x, p01.y);
                af[mi][2] = packh2(p10.x, p10.y);
                af[mi][3] = packh2(p11.x, p11.y);
            }
            #pragma unroll
            for (int mi = 0; mi < 2; mi++)
                #pragma unroll
                for (int ni = 0; ni < 8; ni++) {
                    unsigned bf[2] = { bw0[ni], bw1[ni] };
                    mma_f16(c[mi][ni], af[mi], bf);
                }
        }
        __syncthreads();
    }

    // epilogue (column mapping: ni -> n0w + ni*8 + g; validated R7/R11)
    #pragma unroll
    for (int mi = 0; mi < 2; mi++) {
        #pragma unroll
        for (int ni = 0; ni < 8; ni++) {
            int cc = col0 + n0w + ni*8 + 2*tg;
            float bx = bias[cc], by = bias[cc+1];
            float vx0 = (c[mi][ni][0] + bx) * scale;
            float vy0 = (c[mi][ni][1] + by) * scale;
            float vx1 = (c[mi][ni][2] + bx) * scale;
            float vy1 = (c[mi][ni][3] + by) * scale;
            int r0_ = row0 + m0w + mi*16 + g;           // rr=0 row; rr=1 is r0_+8

            if (MODE == 0) {
                float* out = (float*)outv;
                *(float2*)&out[(size_t)r0_ * Dsz + cc]     = make_float2(vx0, vy0);
                *(float2*)&out[(size_t)(r0_+8) * Dsz + cc] = make_float2(vx1, vy1);
            } else if (MODE == 1) {
                float* out = (float*)outv;
                int h_ = cc >> 6, dh = cc & (DHs-1);
                int b0_ = r0_ >> 11, s0 = r0_ & (Ssz-1);
                size_t base0 = (((size_t)(b0_*Hn + h_) * Ssz) + s0) * DHs;
                *(float2*)&out[base0 + dh]           = make_float2(vx0, vy0);
                *(float2*)&out[base0 + 8*DHs + dh]   = make_float2(vx1, vy1);
            } else if (MODE == 2) {
                // V: pack (r0_, r0_+8) = (kappa, kappa+8) pairs
                unsigned* o16 = (unsigned*)outv;
                int h_ = cc >> 6, dh = cc & (DHs-1);          // dh even
                int b_ = r0_ >> 11, s0 = r0_ & (Ssz-1);       // bit3(s0)=0
                int w = (((s0 & 63) >> 4) << 3) | (s0 & 7);
                int p0 = ((dh & 7) << 3) | (dh >> 3);         // pi64(dh)
                size_t idx = ((size_t)(b_*Hn + h_) * (Ssz/2)
                              + ((size_t)(s0 >> 6) << 5) + w) * 64 + p0;
                o16[idx]     = packh2(vx0, vx1);
                o16[idx + 8] = packh2(vy0, vy1);              // pi64(dh+1)=p0+8
            } else {
                // MODE 3: K -> [b,h,dd,s], word = half2 of d-pair (cc, cc+1)
                unsigned* o16 = (unsigned*)outv;
                int h_ = cc >> 6, dd = (cc & (DHs-1)) >> 1;
                int b0_ = r0_ >> 11;
                size_t base = ((size_t)(b0_*Hn + h_) * 32 + dd) * Ssz;
                o16[base + (r0_ & (Ssz-1))]       = packh2(vx0, vy0);
                o16[base + ((r0_+8) & (Ssz-1))]   = packh2(vx1, vy1);
            }
        }
    }
}

// ---------------------------------------------------------------------------
// FP16 flash attention. QK^T and PV via m16n8k16; P stays in registers
// (C-fragment of QK == A-fragment of PV after pairwise packh2 — FA2 property,
// conventions validated by R11's GEMM).
// K16 tile [32 dd][64 s] half2; V16 tile [32 w][64 pi64(dh)] half2; both pure
// cp.async with chunk-XOR swizzle; all fragment reads LDS.128 conflict-free.
// S instance nt col n -> actual kv 8n+nt (plain K16 cols); PV pairs match
// V16's (kappa, kappa+8) words by construction.
// ---------------------------------------------------------------------------
#define ATTN_SMEM (4*32*64*4)   // 32,768 B

__global__ __launch_bounds__(256, 2)
void attn_f16(const float* __restrict__ Q, const unsigned* __restrict__ K16,
              const unsigned* __restrict__ V16, float* __restrict__ O)
{
    extern __shared__ unsigned smu[];
    unsigned* Kt = smu;               // [2][32][64]
    unsigned* Vs = smu + 2*32*64;     // [2][32][64]

    const int tid  = threadIdx.x;
    const int lane = tid & 31;
    const int warp = tid >> 5;
    const int g  = lane >> 2;
    const int tg = lane & 3;
    const int r0 = warp * 16 + g;

    const int q0 = blockIdx.x * 128;
    const int h = blockIdx.y, b = blockIdx.z;
    const size_t bh = (size_t)(b*Hn + h);
    const float*    Qg = Q   + bh * Ssz * DHs;
    const unsigned* Kg = K16 + bh * 32 * Ssz;
    const unsigned* Vg = V16 + bh * (Ssz/2) * 64;

    const int sig = (tg & 1) | ((tg & 2) << 1);
    const int pk0 = ((2*g)     ^ sig) << 2;
    const int pk1 = ((2*g + 1) ^ sig) << 2;

    // ---- Q fragments: fp32 gmem -> packed half2 regs (once) ----
    unsigned aq[4][4];
    {
        const float* Qr0 = &Qg[(size_t)(q0 + r0) * DHs];
        const float* Qr1 = &Qg[(size_t)(q0 + r0 + 8) * DHs];
        #pragma unroll
        for (int ks = 0; ks < 4; ks++) {
            float2 x0 = *(const float2*)&Qr0[16*ks + 2*tg];
            float2 x1 = *(const float2*)&Qr1[16*ks + 2*tg];
            float2 x2 = *(const float2*)&Qr0[16*ks + 2*tg + 8];
            float2 x3 = *(const float2*)&Qr1[16*ks + 2*tg + 8];
            aq[ks][0] = packh2(x0.x, x0.y);
            aq[ks][1] = packh2(x1.x, x1.y);
            aq[ks][2] = packh2(x2.x, x2.y);
            aq[ks][3] = packh2(x3.x, x3.y);
        }
    }

    auto load_tile = [&](int t0, int stage) {
        unsigned* Kd = Kt + stage*32*64;
        unsigned* Vd = Vs + stage*32*64;
        #pragma unroll
        for (int i = 0; i < 2; i++) {
            int idx = tid + i*256;
            int w = idx >> 4, c = idx & 15;
            int sk = (w & 1) | ((w & 2) << 1);
            cp_async16(&Kd[w*64 + ((c ^ sk) << 2)],
                       &Kg[(size_t)w * Ssz + t0 + 4*c]);
            int sv = ((w >> 3) & 1) | (((w >> 3) & 2) << 1);
            cp_async16(&Vd[w*64 + ((c ^ sv) << 2)],
                       &Vg[(size_t)(((t0 >> 6) << 5) + w) * 64 + 4*c]);
        }
    };

    load_tile(0, 0);   CP_COMMIT();
    load_tile(64, 1);  CP_COMMIT();

    float o[8][4] = {};
    float m0 = -1e30f, m1 = -1e30f, l0 = 0.0f, l1 = 0.0f;

    const int NTILE = Ssz / 64;   // 32
    for (int t = 0; t < NTILE; t++) {
        if (t + 1 < NTILE) { CP_WAIT1(); } else { CP_WAIT0(); }
        __syncthreads();

        const unsigned* Ktp = Kt + (t & 1)*32*64;
        const unsigned* Vsp = Vs + (t & 1)*32*64;

        // ---- S = Q @ K^T (fp16 k16) ----
        float s[8][4] = {};
        #pragma unroll
        for (int ks = 0; ks < 4; ks++) {
            unsigned bw0[8], bw1[8];
            const unsigned* Kr0 = &Ktp[(8*ks + tg)*64];
            const unsigned* Kr1 = &Ktp[(8*ks + tg + 4)*64];
            *(uint4*)&bw0[0] = *(const uint4*)&Kr0[pk0];
            *(uint4*)&bw0[4] = *(const uint4*)&Kr0[pk1];
            *(uint4*)&bw1[0] = *(const uint4*)&Kr1[pk0];
            *(uint4*)&bw1[4] = *(const uint4*)&Kr1[pk1];
            #pragma unroll
            for (int nt = 0; nt < 8; nt++) {
                unsigned bf[2] = { bw0[nt], bw1[nt] };
                mma_f16(s[nt], aq[ks], bf);
            }
        }

        // ---- online softmax (base-2; Q pre-scaled by log2e/8) ----
        float rm0 = -1e30f, rm1 = -1e30f;
        #pragma unroll
        for (int nt = 0; nt < 8; nt++) {
            rm0 = fmaxf(rm0, fmaxf(s[nt][0], s[nt][1]));
            rm1 = fmaxf(rm1, fmaxf(s[nt][2], s[nt][3]));
        }
        rm0 = fmaxf(rm0, __shfl_xor_sync(0xffffffffu, rm0, 1));
        rm0 = fmaxf(rm0, __shfl_xor_sync(0xffffffffu, rm0, 2));
        rm1 = fmaxf(rm1, __shfl_xor_sync(0xffffffffu, rm1, 1));
        rm1 = fmaxf(rm1, __shfl_xor_sync(0xffffffffu, rm1, 2));

        float mn0 = fmaxf(m0, rm0), mn1 = fmaxf(m1, rm1);
        float al0 = ex2(m0 - mn0), al1 = ex2(m1 - mn1);
        m0 = mn0; m1 = mn1;

        float rs0 = 0.0f, rs1 = 0.0f;
        #pragma unroll
        for (int nt = 0; nt < 8; nt++) {
            s[nt][0] = ex2(s[nt][0] - m0);
            s[nt][1] = ex2(s[nt][1] - m0);
            s[nt][2] = ex2(s[nt][2] - m1);
            s[nt][3] = ex2(s[nt][3] - m1);
            rs0 += s[nt][0] + s[nt][1];
            rs1 += s[nt][2] + s[nt][3];
        }
        rs0 += __shfl_xor_sync(0xffffffffu, rs0, 1);
        rs0 += __shfl_xor_sync(0xffffffffu, rs0, 2);
        rs1 += __shfl_xor_sync(0xffffffffu, rs1, 1);
        rs1 += __shfl_xor_sync(0xffffffffu, rs1, 2);

        l0 = l0 * al0 + rs0;
        l1 = l1 * al1 + rs1;
        #pragma unroll
        for (int nt = 0; nt < 8; nt++) {
            o[nt][0] *= al0; o[nt][1] *= al0;
            o[nt][2] *= al1; o[nt][3] *= al1;
        }

        // ---- P: C-fragment -> A-fragment, registers only ----
        unsigned pf[8][2];
        #pragma unroll
        for (int nt = 0; nt < 8; nt++) {
            pf[nt][0] = packh2(s[nt][0], s[nt][1]);   // row g,   kv pair (kappa, kappa+8)
            pf[nt][1] = packh2(s[nt][2], s[nt][3]);   // row g+8, same pair
        }

        // ---- O += P @ V (fp16 k16) ----
        #pragma unroll
        for (int ks = 0; ks < 4; ks++) {
            unsigned bw0[8], bw1[8];
            const unsigned* Vr0 = &Vsp[(8*tg + 2*ks)*64];
            const unsigned* Vr1 = &Vsp[(8*tg + 2*ks + 1)*64];
            *(uint4*)&bw0[0] = *(const uint4*)&Vr0[pk0];
            *(uint4*)&bw0[4] = *(const uint4*)&Vr0[pk1];
            *(uint4*)&bw1[0] = *(const uint4*)&Vr1[pk0];
            *(uint4*)&bw1[4] = *(const uint4*)&Vr1[pk1];
            unsigned a[4] = { pf[2*ks][0], pf[2*ks][1], pf[2*ks+1][0], pf[2*ks+1][1] };
            #pragma unroll
            for (int nt = 0; nt < 8; nt++) {
                unsigned bf[2] = { bw0[nt], bw1[nt] };
                mma_f16(o[nt], a, bf);
            }
        }

        __syncthreads();
        if (t + 2 < NTILE) {
            load_tile((t+2)*64, t & 1);
            CP_COMMIT();
        }
    }

    // ---- normalize + write O: plain [B,S,H*DH] fp32 (col nt*8+2tg) ----
    float inv0 = 1.0f / l0, inv1 = 1.0f / l1;
    size_t ob0 = ((size_t)(b*Ssz + q0 + r0)) * Dsz + h*DHs;
    size_t ob1 = ((size_t)(b*Ssz + q0 + r0 + 8)) * Dsz + h*DHs;
    #pragma unroll
    for (int nt = 0; nt < 8; nt++) {
        int n = nt*8 + 2*tg;
        *(float2*)&O[ob0 + n] = make_float2(o[nt][0]*inv0, o[nt][1]*inv0);
        *(float2*)&O[ob1 + n] = make_float2(o[nt][2]*inv1, o[nt][3]*inv1);
    }
}

// ---------------------------------------------------------------------------

extern "C" void kernel_launch(void* const* d_in, const int* in_sizes, int n_in,
                              void* d_out, int out_size)
{
    (void)in_sizes; (void)n_in; (void)out_size;
    const float* queries = (const float*)d_in[0];
    const float* keys    = (const float*)d_in[1];
    const float* values  = (const float*)d_in[2];
    const float* Wq = (const float*)d_in[3];
    const float* bq = (const float*)d_in[4];
    const float* Wk = (const float*)d_in[5];
    const float* bk = (const float*)d_in[6];
    const float* Wv = (const float*)d_in[7];
    const float* bv = (const float*)d_in[8];
    const float* Wo = (const float*)d_in[9];
    const float* bo = (const float*)d_in[10];
    float* out = (float*)d_out;

    void *pwq,*pwk,*pwv,*pwo,*pq,*pk,*pv,*po;
    cudaGetSymbolAddress(&pwq, g_wq16); cudaGetSymbolAddress(&pwk, g_wk16);
    cudaGetSymbolAddress(&pwv, g_wv16); cudaGetSymbolAddress(&pwo, g_wo16);
    cudaGetSymbolAddress(&pq, g_q);     cudaGetSymbolAddress(&pk, g_k16);
    cudaGetSymbolAddress(&pv, g_v16);   cudaGetSymbolAddress(&po, g_o);

    cudaFuncSetAttribute(gemm_f16<0>, cudaFuncAttributeMaxDynamicSharedMemorySize, GEMM_SMEM);
    cudaFuncSetAttribute(gemm_f16<1>, cudaFuncAttributeMaxDynamicSharedMemorySize, GEMM_SMEM);
    cudaFuncSetAttribute(gemm_f16<2>, cudaFuncAttributeMaxDynamicSharedMemorySize, GEMM_SMEM);
    cudaFuncSetAttribute(gemm_f16<3>, cudaFuncAttributeMaxDynamicSharedMemorySize, GEMM_SMEM);
    cudaFuncSetAttribute(attn_f16,    cudaFuncAttributeMaxDynamicSharedMemorySize, ATTN_SMEM);

    // weight converts (fp16 pack + pi64 n-permute; ~5us each)
    cvt_w16<<<512, 256>>>(Wq, (unsigned*)pwq);
    cvt_w16<<<512, 256>>>(Wk, (unsigned*)pwk);
    cvt_w16<<<512, 256>>>(Wv, (unsigned*)pwv);
    cvt_w16<<<512, 256>>>(Wo, (unsigned*)pwo);

    dim3 ggrid(Dsz/128, Mrows/128);   // (8, 32)
    const float qscale = 0.125f * 1.4426950408889634f;   // log2e / sqrt(64)

    gemm_f16<1><<<ggrid, 256, GEMM_SMEM>>>(queries, (const unsigned*)pwq, bq, pq, qscale);
    gemm_f16<3><<<ggrid, 256, GEMM_SMEM>>>(keys,    (const unsigned*)pwk, bk, pk, 1.0f);
    gemm_f16<2><<<ggrid, 256, GEMM_SMEM>>>(values,  (const unsigned*)pwv, bv, pv, 1.0f);

    dim3 agrid(Ssz/128, Hn, Bsz);     // (16, 16, 2)
    attn_f16<<<agrid, 256, ATTN_SMEM>>>((const float*)pq, (const unsigned*)pk,
                                        (const unsigned*)pv, (float*)po);

    gemm_f16<0><<<ggrid, 256, GEMM_SMEM>>>((const float*)po, (const unsigned*)pwo, bo, out, 1.0f);
}

// round 13
// speedup vs baseline: 2.1433x; 1.0279x over previous
#include <cuda_runtime.h>
#include <cuda_fp16.h>
#include <math.h>

#define Bsz 2
#define Ssz 2048
#define Dsz 1024
#define Hn  16
#define DHs 64
#define Mrows (Bsz*Ssz)

// Scratch (static device globals; no runtime allocation)
__device__ unsigned g_wq16[(Dsz/2)*Dsz];  // fp16-packed k-pairs, pi64 n-permute
__device__ unsigned g_wk16[(Dsz/2)*Dsz];
__device__ unsigned g_wv16[(Dsz/2)*Dsz];
__device__ unsigned g_wo16[(Dsz/2)*Dsz];
__device__ unsigned g_q16[Mrows*Dsz/2];    // [B,H,S,32w]: word = half2(q[2w],q[2w+1])
__device__ unsigned g_k16[Mrows*Dsz/2];    // [B,H,32(dd),S]: (K[2dd][s],K[2dd+1][s])
__device__ unsigned g_v16[Mrows*Dsz/2];    // [B,H,S/2(w),64]: kv-pair x pi64(dh)
__device__ unsigned g_o16[Mrows*Dsz/2];    // [M,512w]: word = half2(o[2w],o[2w+1])

// ---------------------------------------------------------------------------
// helpers
// ---------------------------------------------------------------------------
__device__ __forceinline__ float ex2(float x) {
    float r; asm("ex2.approx.ftz.f32 %0, %1;" : "=f"(r) : "f"(x)); return r;
}
__device__ __forceinline__ unsigned packh2(float lo, float hi) {
    __half2 h = __floats2half2_rn(lo, hi);
    return *reinterpret_cast<unsigned*>(&h);
}
__device__ __forceinline__ void mma_f16(float* c, const unsigned* a, const unsigned* b) {
    asm volatile(
        "mma.sync.aligned.m16n8k16.row.col.f32.f16.f16.f32 "
        "{%0,%1,%2,%3}, {%4,%5,%6,%7}, {%8,%9}, {%0,%1,%2,%3};"
        : "+f"(c[0]), "+f"(c[1]), "+f"(c[2]), "+f"(c[3])
        : "r"(a[0]), "r"(a[1]), "r"(a[2]), "r"(a[3]), "r"(b[0]), "r"(b[1]));
}
__device__ __forceinline__ void cp_async16(void* smem, const void* gmem) {
    unsigned s = (unsigned)__cvta_generic_to_shared(smem);
    asm volatile("cp.async.cg.shared.global [%0], [%1], 16;" :: "r"(s), "l"(gmem));
}
#define CP_COMMIT() asm volatile("cp.async.commit_group;")
#define CP_WAIT1()  asm volatile("cp.async.wait_group 1;")
#define CP_WAIT0()  asm volatile("cp.async.wait_group 0;")

// ---------------------------------------------------------------------------
// Weight convert, ALL FOUR in one launch (R11 body, validated).
// ---------------------------------------------------------------------------
__global__ void cvt_w16x4(const float* __restrict__ s0, const float* __restrict__ s1,
                          const float* __restrict__ s2, const float* __restrict__ s3,
                          unsigned* __restrict__ d0, unsigned* __restrict__ d1,
                          unsigned* __restrict__ d2, unsigned* __restrict__ d3)
{
    int wsel = blockIdx.x >> 9;
    const float* in = (wsel == 0) ? s0 : (wsel == 1) ? s1 : (wsel == 2) ? s2 : s3;
    unsigned* out   = (wsel == 0) ? d0 : (wsel == 1) ? d1 : (wsel == 2) ? d2 : d3;
    int gid = (blockIdx.x & 511) * 256 + threadIdx.x;
    int kk = gid >> 8;
    int n  = (gid & 255) * 4;
    float4 v0 = *(const float4*)&in[(size_t)(2*kk)     * Dsz + n];
    float4 v1 = *(const float4*)&in[(size_t)(2*kk + 1) * Dsz + n];
    float a0[4] = {v0.x, v0.y, v0.z, v0.w};
    float a1[4] = {v1.x, v1.y, v1.z, v1.w};
    size_t base = (size_t)kk * Dsz + (n & ~63);
    #pragma unroll
    for (int i = 0; i < 4; i++) {
        int x = (n & 63) + i;
        int p = ((x & 7) << 3) | (x >> 3);
        out[base + p] = packh2(a0[i], a1[i]);
    }
}

// ---------------------------------------------------------------------------
// FP16 GEMM (R11/R12 main loop, validated). A16=0: fp32 A input (pack in
// fragment path). A16=1: pre-packed half2 A input (g_o16), pitch-20-word smem,
// scalar-LDS fragments (banks 20g+tg mod 32 all distinct: conflict-free).
// MODE 0: plain [M,1024] fp32 out
// MODE 1: Q -> g_q16 packed half2 words [B,H,S,32w]
// MODE 2: V -> g_v16 (kv-pair words, pi64(dh))       [R12, validated]
// MODE 3: K -> g_k16 (d-pair words, [b,h,dd,s])      [R12, validated]
// ---------------------------------------------------------------------------
#define A_PITCH 40
#define GEMM_SMEM   ((2*128*A_PITCH + 2*16*128) * 4)   // 57,344 B
#define GEMM_SMEM16 ((2*128*20 + 2*16*128) * 4)        // 36,864 B

template<int MODE, int A16>
__global__ __launch_bounds__(256, 2)
void gemm_f16(const void* __restrict__ Xv, const unsigned* __restrict__ Wh,
              const float* __restrict__ bias, void* __restrict__ outv,
              float scale)
{
    extern __shared__ float sm[];
    float*    As   = sm;                                        // A16=0: [2][128][40] fp32
    unsigned* As16 = (unsigned*)sm;                             // A16=1: [2][128][20] words
    unsigned* Bs   = A16 ? (unsigned*)(sm + 2*128*20)
                         : (unsigned*)(sm + 2*128*A_PITCH);     // [2][16][128] words

    const int tid  = threadIdx.x;
    const int lane = tid & 31;
    const int warp = tid >> 5;
    const int g  = lane >> 2;
    const int tg = lane & 3;
    const int m0w = (warp >> 1) * 32;
    const int n0w = (warp & 1) * 64;
    const int row0 = blockIdx.y * 128;
    const int col0 = blockIdx.x * 128;

    const int sB = ((tg & 1) << 2) | ((tg >> 1) & 1);
    const int cb = (n0w >> 2) + 2*g;

    float c[2][8][4] = {};

    auto load_stage = [&](int kt, int p) {
        unsigned* Bd = Bs + p*16*128;
        if (A16) {
            unsigned* Ad = As16 + p*128*20;
            const unsigned* X16 = (const unsigned*)Xv;
            #pragma unroll
            for (int i = 0; i < 2; i++) {
                int idx = tid + i*256;
                int r = idx >> 2, wc = idx & 3;
                cp_async16(&Ad[r*20 + wc*4],
                           &X16[(size_t)(row0 + r)*(Dsz/2) + kt*16 + wc*4]);
            }
        } else {
            float* Ad = As + p*128*A_PITCH;
            const float* X = (const float*)Xv;
            #pragma unroll
            for (int i = 0; i < 4; i++) {
                int idx = tid + i*256;
                int r = idx >> 3, c4 = idx & 7;
                cp_async16(&Ad[r*A_PITCH + c4*4],
                           &X[(size_t)(row0 + r)*Dsz + kt*32 + c4*4]);
            }
        }
        #pragma unroll
        for (int i = 0; i < 2; i++) {
            int idx = tid + i*256;
            int r = idx >> 5, cc = idx & 31;
            int s = ((r & 1) << 2) | ((r >> 1) & 1);
            cp_async16(&Bd[r*128 + ((cc ^ s) << 2)],
                       &Wh[(size_t)(kt*16 + r)*Dsz + col0 + (cc << 2)]);
        }
    };

    load_stage(0, 0);
    CP_COMMIT();

    const int NT = Dsz / 32;
    for (int kt = 0; kt < NT; kt++) {
        int p = kt & 1;
        if (kt + 1 < NT) {
            load_stage(kt + 1, p ^ 1);
            CP_COMMIT();
            CP_WAIT1();
        } else {
            CP_WAIT0();
        }
        __syncthreads();

        const unsigned* Bp = Bs + p*16*128;

        #pragma unroll
        for (int ks = 0; ks < 2; ks++) {
            unsigned bw0[8], bw1[8];
            {
                const unsigned* Br0 = &Bp[(8*ks + tg) * 128];
                const unsigned* Br1 = &Bp[(8*ks + tg + 4) * 128];
                *(uint4*)&bw0[0] = *(const uint4*)&Br0[((cb)     ^ sB) << 2];
                *(uint4*)&bw0[4] = *(const uint4*)&Br0[((cb + 1) ^ sB) << 2];
                *(uint4*)&bw1[0] = *(const uint4*)&Br1[((cb)     ^ sB) << 2];
                *(uint4*)&bw1[4] = *(const uint4*)&Br1[((cb + 1) ^ sB) << 2];
            }
            unsigned af[2][4];
            if (A16) {
                const unsigned* Ap16 = As16 + p*128*20;
                #pragma unroll
                for (int mi = 0; mi < 2; mi++) {
                    int r = m0w + mi*16 + g;
                    af[mi][0] = Ap16[r*20 + 8*ks + tg];
                    af[mi][1] = Ap16[(r+8)*20 + 8*ks + tg];
                    af[mi][2] = Ap16[r*20 + 8*ks + tg + 4];
                    af[mi][3] = Ap16[(r+8)*20 + 8*ks + tg + 4];
                }
            } else {
                const float* Ap = As + p*128*A_PITCH;
                #pragma unroll
                for (int mi = 0; mi < 2; mi++) {
                    int r = m0w + mi*16 + g;
                    int kc = 16*ks + 2*tg;
                    float2 p00 = *(const float2*)&Ap[r*A_PITCH + kc];
                    float2 p01 = *(const float2*)&Ap[(r+8)*A_PITCH + kc];
                    float2 p10 = *(const float2*)&Ap[r*A_PITCH + kc + 8];
                    float2 p11 = *(const float2*)&Ap[(r+8)*A_PITCH + kc + 8];
                    af[mi][0] = packh2(p00.x, p00.y);
                    af[mi][1] = packh2(p01.x, p01.y);
                    af[mi][2] = packh2(p10.x, p10.y);
                    af[mi][3] = packh2(p11.x, p11.y);
                }
            }
            #pragma unroll
            for (int mi = 0; mi < 2; mi++)
                #pragma unroll
                for (int ni = 0; ni < 8; ni++) {
                    unsigned bf[2] = { bw0[ni], bw1[ni] };
                    mma_f16(c[mi][ni], af[mi], bf);
                }
        }
        __syncthreads();
    }

    // epilogue (column mapping: ni -> n0w + ni*8 + g; validated R7/R11/R12)
    #pragma unroll
    for (int mi = 0; mi < 2; mi++) {
        #pragma unroll
        for (int ni = 0; ni < 8; ni++) {
            int cc = col0 + n0w + ni*8 + 2*tg;
            float bx = bias[cc], by = bias[cc+1];
            float vx0 = (c[mi][ni][0] + bx) * scale;
            float vy0 = (c[mi][ni][1] + by) * scale;
            float vx1 = (c[mi][ni][2] + bx) * scale;
            float vy1 = (c[mi][ni][3] + by) * scale;
            int r0_ = row0 + m0w + mi*16 + g;

            if (MODE == 0) {
                float* out = (float*)outv;
                *(float2*)&out[(size_t)r0_ * Dsz + cc]     = make_float2(vx0, vy0);
                *(float2*)&out[(size_t)(r0_+8) * Dsz + cc] = make_float2(vx1, vy1);
            } else if (MODE == 1) {
                // Q -> packed half2 words [B,H,S,32w]
                unsigned* o16 = (unsigned*)outv;
                int h_ = cc >> 6, dh = cc & (DHs-1);
                int b0_ = r0_ >> 11, s0 = r0_ & (Ssz-1);
                size_t base0 = (((size_t)(b0_*Hn + h_) * Ssz) + s0) * 32 + (dh >> 1);
                o16[base0]        = packh2(vx0, vy0);
                o16[base0 + 8*32] = packh2(vx1, vy1);
            } else if (MODE == 2) {
                unsigned* o16 = (unsigned*)outv;
                int h_ = cc >> 6, dh = cc & (DHs-1);
                int b_ = r0_ >> 11, s0 = r0_ & (Ssz-1);
                int w = (((s0 & 63) >> 4) << 3) | (s0 & 7);
                int p0 = ((dh & 7) << 3) | (dh >> 3);
                size_t idx = ((size_t)(b_*Hn + h_) * (Ssz/2)
                              + ((size_t)(s0 >> 6) << 5) + w) * 64 + p0;
                o16[idx]     = packh2(vx0, vx1);
                o16[idx + 8] = packh2(vy0, vy1);
            } else {
                unsigned* o16 = (unsigned*)outv;
                int h_ = cc >> 6, dd = (cc & (DHs-1)) >> 1;
                int b0_ = r0_ >> 11;
                size_t base = ((size_t)(b0_*Hn + h_) * 32 + dd) * Ssz;
                o16[base + (r0_ & (Ssz-1))]     = packh2(vx0, vy0);
                o16[base + ((r0_+8) & (Ssz-1))] = packh2(vx1, vy1);
            }
        }
    }
}

// ---------------------------------------------------------------------------
// FP16 flash attention (R12 compute, validated; 2 interface changes):
//  - Q input now pre-packed half2 words (16 scalar LDG once, zero packs)
//  - O output packed half2 words in final-GEMM A-fragment layout
// ---------------------------------------------------------------------------
#define ATTN_SMEM (4*32*64*4)   // 32,768 B

__global__ __launch_bounds__(256, 2)
void attn_f16(const unsigned* __restrict__ Q16, const unsigned* __restrict__ K16,
              const unsigned* __restrict__ V16, unsigned* __restrict__ O16)
{
    extern __shared__ unsigned smu[];
    unsigned* Kt = smu;               // [2][32][64]
    unsigned* Vs = smu + 2*32*64;     // [2][32][64]

    const int tid  = threadIdx.x;
    const int lane = tid & 31;
    const int warp = tid >> 5;
    const int g  = lane >> 2;
    const int tg = lane & 3;
    const int r0 = warp * 16 + g;

    const int q0 = blockIdx.x * 128;
    const int h = blockIdx.y, b = blockIdx.z;
    const size_t bh = (size_t)(b*Hn + h);
    const unsigned* Qg = Q16 + bh * Ssz * 32;
    const unsigned* Kg = K16 + bh * 32 * Ssz;
    const unsigned* Vg = V16 + bh * (Ssz/2) * 64;

    const int sig = (tg & 1) | ((tg & 2) << 1);
    const int pk0 = ((2*g)     ^ sig) << 2;
    const int pk1 = ((2*g + 1) ^ sig) << 2;

    // ---- Q fragments: pre-packed words, 16 scalar LDG once ----
    unsigned aq[4][4];
    {
        const unsigned* Qw0 = &Qg[(size_t)(q0 + r0) * 32];
        const unsigned* Qw1 = &Qg[(size_t)(q0 + r0 + 8) * 32];
        #pragma unroll
        for (int ks = 0; ks < 4; ks++) {
            aq[ks][0] = Qw0[8*ks + tg];
            aq[ks][1] = Qw1[8*ks + tg];
            aq[ks][2] = Qw0[8*ks + tg + 4];
            aq[ks][3] = Qw1[8*ks + tg + 4];
        }
    }

    auto load_tile = [&](int t0, int stage) {
        unsigned* Kd = Kt + stage*32*64;
        unsigned* Vd = Vs + stage*32*64;
        #pragma unroll
        for (int i = 0; i < 2; i++) {
            int idx = tid + i*256;
            int w = idx >> 4, c = idx & 15;
            int sk = (w & 1) | ((w & 2) << 1);
            cp_async16(&Kd[w*64 + ((c ^ sk) << 2)],
                       &Kg[(size_t)w * Ssz + t0 + 4*c]);
            int sv = ((w >> 3) & 1) | (((w >> 3) & 2) << 1);
            cp_async16(&Vd[w*64 + ((c ^ sv) << 2)],
                       &Vg[(size_t)(((t0 >> 6) << 5) + w) * 64 + 4*c]);
        }
    };

    load_tile(0, 0);   CP_COMMIT();
    load_tile(64, 1);  CP_COMMIT();

    float o[8][4] = {};
    float m0 = -1e30f, m1 = -1e30f, l0 = 0.0f, l1 = 0.0f;

    const int NTILE = Ssz / 64;   // 32
    for (int t = 0; t < NTILE; t++) {
        if (t + 1 < NTILE) { CP_WAIT1(); } else { CP_WAIT0(); }
        __syncthreads();

        const unsigned* Ktp = Kt + (t & 1)*32*64;
        const unsigned* Vsp = Vs + (t & 1)*32*64;

        float s[8][4] = {};
        #pragma unroll
        for (int ks = 0; ks < 4; ks++) {
            unsigned bw0[8], bw1[8];
            const unsigned* Kr0 = &Ktp[(8*ks + tg)*64];
            const unsigned* Kr1 = &Ktp[(8*ks + tg + 4)*64];
            *(uint4*)&bw0[0] = *(const uint4*)&Kr0[pk0];
            *(uint4*)&bw0[4] = *(const uint4*)&Kr0[pk1];
            *(uint4*)&bw1[0] = *(const uint4*)&Kr1[pk0];
            *(uint4*)&bw1[4] = *(const uint4*)&Kr1[pk1];
            #pragma unroll
            for (int nt = 0; nt < 8; nt++) {
                unsigned bf[2] = { bw0[nt], bw1[nt] };
                mma_f16(s[nt], aq[ks], bf);
            }
        }

        float rm0 = -1e30f, rm1 = -1e30f;
        #pragma unroll
        for (int nt = 0; nt < 8; nt++) {
            rm0 = fmaxf(rm0, fmaxf(s[nt][0], s[nt][1]));
            rm1 = fmaxf(rm1, fmaxf(s[nt][2], s[nt][3]));
        }
        rm0 = fmaxf(rm0, __shfl_xor_sync(0xffffffffu, rm0, 1));
        rm0 = fmaxf(rm0, __shfl_xor_sync(0xffffffffu, rm0, 2));
        rm1 = fmaxf(rm1, __shfl_xor_sync(0xffffffffu, rm1, 1));
        rm1 = fmaxf(rm1, __shfl_xor_sync(0xffffffffu, rm1, 2));

        float mn0 = fmaxf(m0, rm0), mn1 = fmaxf(m1, rm1);
        float al0 = ex2(m0 - mn0), al1 = ex2(m1 - mn1);
        m0 = mn0; m1 = mn1;

        float rs0 = 0.0f, rs1 = 0.0f;
        #pragma unroll
        for (int nt = 0; nt < 8; nt++) {
            s[nt][0] = ex2(s[nt][0] - m0);
            s[nt][1] = ex2(s[nt][1] - m0);
            s[nt][2] = ex2(s[nt][2] - m1);
            s[nt][3] = ex2(s[nt][3] - m1);
            rs0 += s[nt][0] + s[nt][1];
            rs1 += s[nt][2] + s[nt][3];
        }
        rs0 += __shfl_xor_sync(0xffffffffu, rs0, 1);
        rs0 += __shfl_xor_sync(0xffffffffu, rs0, 2);
        rs1 += __shfl_xor_sync(0xffffffffu, rs1, 1);
        rs1 += __shfl_xor_sync(0xffffffffu, rs1, 2);

        l0 = l0 * al0 + rs0;
        l1 = l1 * al1 + rs1;
        #pragma unroll
        for (int nt = 0; nt < 8; nt++) {
            o[nt][0] *= al0; o[nt][1] *= al0;
            o[nt][2] *= al1; o[nt][3] *= al1;
        }

        unsigned pf[8][2];
        #pragma unroll
        for (int nt = 0; nt < 8; nt++) {
            pf[nt][0] = packh2(s[nt][0], s[nt][1]);
            pf[nt][1] = packh2(s[nt][2], s[nt][3]);
        }

        #pragma unroll
        for (int ks = 0; ks < 4; ks++) {
            unsigned bw0[8], bw1[8];
            const unsigned* Vr0 = &Vsp[(8*tg + 2*ks)*64];
            const unsigned* Vr1 = &Vsp[(8*tg + 2*ks + 1)*64];
            *(uint4*)&bw0[0] = *(const uint4*)&Vr0[pk0];
            *(uint4*)&bw0[4] = *(const uint4*)&Vr0[pk1];
            *(uint4*)&bw1[0] = *(const uint4*)&Vr1[pk0];
            *(uint4*)&bw1[4] = *(const uint4*)&Vr1[pk1];
            unsigned a[4] = { pf[2*ks][0], pf[2*ks][1], pf[2*ks+1][0], pf[2*ks+1][1] };
            #pragma unroll
            for (int nt = 0; nt < 8; nt++) {
                unsigned bf[2] = { bw0[nt], bw1[nt] };
                mma_f16(o[nt], a, bf);
            }
        }

        __syncthreads();
        if (t + 2 < NTILE) {
            load_tile((t+2)*64, t & 1);
            CP_COMMIT();
        }
    }

    // ---- normalize + write O as packed half2 words [M, 512w] ----
    float inv0 = 1.0f / l0, inv1 = 1.0f / l1;
    size_t ob0 = ((size_t)(b*Ssz + q0 + r0)) * (Dsz/2) + h*32;
    size_t ob1 = ((size_t)(b*Ssz + q0 + r0 + 8)) * (Dsz/2) + h*32;
    #pragma unroll
    for (int nt = 0; nt < 8; nt++) {
        int w = nt*4 + tg;
        O16[ob0 + w] = packh2(o[nt][0]*inv0, o[nt][1]*inv0);
        O16[ob1 + w] = packh2(o[nt][2]*inv1, o[nt][3]*inv1);
    }
}

// ---------------------------------------------------------------------------

extern "C" void kernel_launch(void* const* d_in, const int* in_sizes, int n_in,
                              void* d_out, int out_size)
{
    (void)in_sizes; (void)n_in; (void)out_size;
    const float* queries = (const float*)d_in[0];
    const float* keys    = (const float*)d_in[1];
    const float* values  = (const float*)d_in[2];
    const float* Wq = (const float*)d_in[3];
    const float* bq = (const float*)d_in[4];
    const float* Wk = (const float*)d_in[5];
    const float* bk = (const float*)d_in[6];
    const float* Wv = (const float*)d_in[7];
    const float* bv = (const float*)d_in[8];
    const float* Wo = (const float*)d_in[9];
    const float* bo = (const float*)d_in[10];
    float* out = (float*)d_out;

    void *pwq,*pwk,*pwv,*pwo,*pq,*pk,*pv,*po;
    cudaGetSymbolAddress(&pwq, g_wq16); cudaGetSymbolAddress(&pwk, g_wk16);
    cudaGetSymbolAddress(&pwv, g_wv16); cudaGetSymbolAddress(&pwo, g_wo16);
    cudaGetSymbolAddress(&pq, g_q16);   cudaGetSymbolAddress(&pk, g_k16);
    cudaGetSymbolAddress(&pv, g_v16);   cudaGetSymbolAddress(&po, g_o16);

    cudaFuncSetAttribute((const void*)gemm_f16<0,1>, cudaFuncAttributeMaxDynamicSharedMemorySize, GEMM_SMEM16);
    cudaFuncSetAttribute((const void*)gemm_f16<1,0>, cudaFuncAttributeMaxDynamicSharedMemorySize, GEMM_SMEM);
    cudaFuncSetAttribute((const void*)gemm_f16<2,0>, cudaFuncAttributeMaxDynamicSharedMemorySize, GEMM_SMEM);
    cudaFuncSetAttribute((const void*)gemm_f16<3,0>, cudaFuncAttributeMaxDynamicSharedMemorySize, GEMM_SMEM);
    cudaFuncSetAttribute((const void*)attn_f16,      cudaFuncAttributeMaxDynamicSharedMemorySize, ATTN_SMEM);

    // launch 1: all four weight converts in one kernel
    cvt_w16x4<<<2048, 256>>>(Wq, Wk, Wv, Wo,
                             (unsigned*)pwq, (unsigned*)pwk,
                             (unsigned*)pwv, (unsigned*)pwo);

    dim3 ggrid(Dsz/128, Mrows/128);   // (8, 32)
    const float qscale = 0.125f * 1.4426950408889634f;   // log2e / sqrt(64)

    // launches 2-4: projections
    gemm_f16<1,0><<<ggrid, 256, GEMM_SMEM>>>(queries, (const unsigned*)pwq, bq, pq, qscale);
    gemm_f16<3,0><<<ggrid, 256, GEMM_SMEM>>>(keys,    (const unsigned*)pwk, bk, pk, 1.0f);
    gemm_f16<2,0><<<ggrid, 256, GEMM_SMEM>>>(values,  (const unsigned*)pwv, bv, pv, 1.0f);

    // launch 5: attention
    dim3 agrid(Ssz/128, Hn, Bsz);     // (16, 16, 2)
    attn_f16<<<agrid, 256, ATTN_SMEM>>>((const unsigned*)pq, (const unsigned*)pk,
                                        (const unsigned*)pv, (unsigned*)po);

    // launch 6: final projection (pre-packed fp16 A path)
    gemm_f16<0,1><<<ggrid, 256, GEMM_SMEM16>>>((const void*)po, (const unsigned*)pwo, bo, out, 1.0f);
}

// round 14
// speedup vs baseline: 2.1632x; 1.0093x over previous
#include <cuda_runtime.h>
#include <cuda_fp16.h>
#include <math.h>

#define Bsz 2
#define Ssz 2048
#define Dsz 1024
#define Hn  16
#define DHs 64
#define Mrows (Bsz*Ssz)

// Scratch (static device globals; no runtime allocation)
__device__ unsigned g_wq16[(Dsz/2)*Dsz];  // fp16-packed k-pairs, pi64 n-permute
__device__ unsigned g_wk16[(Dsz/2)*Dsz];
__device__ unsigned g_wv16[(Dsz/2)*Dsz];
__device__ unsigned g_wo16[(Dsz/2)*Dsz];
__device__ unsigned g_q16[Mrows*Dsz/2];    // [B,H,S,32w]
__device__ unsigned g_k16[Mrows*Dsz/2];    // [B,H,32(dd),S]
__device__ unsigned g_v16[Mrows*Dsz/2];    // [B,H,S/2(w),64]
__device__ unsigned g_o16[Mrows*Dsz/2];    // [M,512w]

// ---------------------------------------------------------------------------
// helpers
// ---------------------------------------------------------------------------
__device__ __forceinline__ float ex2(float x) {
    float r; asm("ex2.approx.ftz.f32 %0, %1;" : "=f"(r) : "f"(x)); return r;
}
__device__ __forceinline__ unsigned packh2(float lo, float hi) {
    __half2 h = __floats2half2_rn(lo, hi);
    return *reinterpret_cast<unsigned*>(&h);
}
__device__ __forceinline__ void mma_f16(float* c, const unsigned* a, const unsigned* b) {
    asm volatile(
        "mma.sync.aligned.m16n8k16.row.col.f32.f16.f16.f32 "
        "{%0,%1,%2,%3}, {%4,%5,%6,%7}, {%8,%9}, {%0,%1,%2,%3};"
        : "+f"(c[0]), "+f"(c[1]), "+f"(c[2]), "+f"(c[3])
        : "r"(a[0]), "r"(a[1]), "r"(a[2]), "r"(a[3]), "r"(b[0]), "r"(b[1]));
}
__device__ __forceinline__ void cp_async16(void* smem, const void* gmem) {
    unsigned s = (unsigned)__cvta_generic_to_shared(smem);
    asm volatile("cp.async.cg.shared.global [%0], [%1], 16;" :: "r"(s), "l"(gmem));
}
#define CP_COMMIT() asm volatile("cp.async.commit_group;")
#define CP_WAIT1()  asm volatile("cp.async.wait_group 1;")
#define CP_WAIT0()  asm volatile("cp.async.wait_group 0;")

// ---------------------------------------------------------------------------
// Weight convert, all four in one launch (R13, validated).
// ---------------------------------------------------------------------------
__global__ void cvt_w16x4(const float* __restrict__ s0, const float* __restrict__ s1,
                          const float* __restrict__ s2, const float* __restrict__ s3,
                          unsigned* __restrict__ d0, unsigned* __restrict__ d1,
                          unsigned* __restrict__ d2, unsigned* __restrict__ d3)
{
    int wsel = blockIdx.x >> 9;
    const float* in = (wsel == 0) ? s0 : (wsel == 1) ? s1 : (wsel == 2) ? s2 : s3;
    unsigned* out   = (wsel == 0) ? d0 : (wsel == 1) ? d1 : (wsel == 2) ? d2 : d3;
    int gid = (blockIdx.x & 511) * 256 + threadIdx.x;
    int kk = gid >> 8;
    int n  = (gid & 255) * 4;
    float4 v0 = *(const float4*)&in[(size_t)(2*kk)     * Dsz + n];
    float4 v1 = *(const float4*)&in[(size_t)(2*kk + 1) * Dsz + n];
    float a0[4] = {v0.x, v0.y, v0.z, v0.w};
    float a1[4] = {v1.x, v1.y, v1.z, v1.w};
    size_t base = (size_t)kk * Dsz + (n & ~63);
    #pragma unroll
    for (int i = 0; i < 4; i++) {
        int x = (n & 63) + i;
        int p = ((x & 7) << 3) | (x >> 3);
        out[base + p] = packh2(a0[i], a1[i]);
    }
}

// ---------------------------------------------------------------------------
// FP16 GEMM, 3-stage cp.async pipeline, ONE __syncthreads per kt.
// Fragment/epilogue algebra byte-compatible with R13 (validated).
// Runtime mode per blockIdx.z (uniform branch, epilogue only):
//   mode 0: plain [M,1024] fp32      mode 1: Q -> g_q16 packed words
//   mode 2: V -> g_v16 kv-pair words mode 3: K -> g_k16 d-pair words
// A16=0: fp32 A input; A16=1: pre-packed half2 A (g_o16), pitch-20 words.
// ---------------------------------------------------------------------------
struct GemmArgs {
    const void*     X[3];
    const unsigned* W[3];
    const float*    bias[3];
    void*           out[3];
    float           scale[3];
    int             mode[3];
};

#define A_PITCH 40
#define GEMM_SMEM   (3*(128*A_PITCH + 16*128) * 4)   // 86,016 B
#define GEMM_SMEM16 (3*(128*20      + 16*128) * 4)   // 55,296 B

template<int A16>
__global__ __launch_bounds__(256, 2)
void gemm_f16m(GemmArgs args)
{
    extern __shared__ float sm[];
    const int APITCH = A16 ? 20 : A_PITCH;            // words vs floats (both 4B)
    float*    As   = sm;                              // [3][128][APITCH]
    unsigned* As16 = (unsigned*)sm;
    unsigned* Bs   = (unsigned*)(sm + 3*128*APITCH);  // [3][16][128]

    const int z = blockIdx.z;
    const void*     Xv   = args.X[z];
    const unsigned* Wh   = args.W[z];
    const float*    bias = args.bias[z];
    void*           outv = args.out[z];
    const float     scale = args.scale[z];
    const int       mode  = args.mode[z];

    const int tid  = threadIdx.x;
    const int lane = tid & 31;
    const int warp = tid >> 5;
    const int g  = lane >> 2;
    const int tg = lane & 3;
    const int m0w = (warp >> 1) * 32;
    const int n0w = (warp & 1) * 64;
    const int row0 = blockIdx.y * 128;
    const int col0 = blockIdx.x * 128;

    const int sB = ((tg & 1) << 2) | ((tg >> 1) & 1);
    const int cb = (n0w >> 2) + 2*g;

    float c[2][8][4] = {};

    auto load_stage = [&](int kt, int st) {
        unsigned* Bd = Bs + st*16*128;
        if (A16) {
            unsigned* Ad = As16 + st*128*20;
            const unsigned* X16 = (const unsigned*)Xv;
            #pragma unroll
            for (int i = 0; i < 2; i++) {
                int idx = tid + i*256;
                int r = idx >> 2, wc = idx & 3;
                cp_async16(&Ad[r*20 + wc*4],
                           &X16[(size_t)(row0 + r)*(Dsz/2) + kt*16 + wc*4]);
            }
        } else {
            float* Ad = As + st*128*A_PITCH;
            const float* X = (const float*)Xv;
            #pragma unroll
            for (int i = 0; i < 4; i++) {
                int idx = tid + i*256;
                int r = idx >> 3, c4 = idx & 7;
                cp_async16(&Ad[r*A_PITCH + c4*4],
                           &X[(size_t)(row0 + r)*Dsz + kt*32 + c4*4]);
            }
        }
        #pragma unroll
        for (int i = 0; i < 2; i++) {
            int idx = tid + i*256;
            int r = idx >> 5, cc = idx & 31;
            int s = ((r & 1) << 2) | ((r >> 1) & 1);
            cp_async16(&Bd[r*128 + ((cc ^ s) << 2)],
                       &Wh[(size_t)(kt*16 + r)*Dsz + col0 + (cc << 2)]);
        }
    };

    load_stage(0, 0); CP_COMMIT();
    load_stage(1, 1); CP_COMMIT();

    const int NT = Dsz / 32;   // 32
    int st = 0, st2 = 2;       // compute stage, prefetch stage (mod 3 counters)
    for (int kt = 0; kt < NT; kt++) {
        if (kt + 1 < NT) { CP_WAIT1(); } else { CP_WAIT0(); }
        __syncthreads();   // stage st ready; all warps done with stage st2 (= kt-1's buffer)

        if (kt + 2 < NT) {
            load_stage(kt + 2, st2);
            CP_COMMIT();
        }

        const unsigned* Bp = Bs + st*16*128;
        #pragma unroll
        for (int ks = 0; ks < 2; ks++) {
            unsigned bw0[8], bw1[8];
            {
                const unsigned* Br0 = &Bp[(8*ks + tg) * 128];
                const unsigned* Br1 = &Bp[(8*ks + tg + 4) * 128];
                *(uint4*)&bw0[0] = *(const uint4*)&Br0[((cb)     ^ sB) << 2];
                *(uint4*)&bw0[4] = *(const uint4*)&Br0[((cb + 1) ^ sB) << 2];
                *(uint4*)&bw1[0] = *(const uint4*)&Br1[((cb)     ^ sB) << 2];
                *(uint4*)&bw1[4] = *(const uint4*)&Br1[((cb + 1) ^ sB) << 2];
            }
            unsigned af[2][4];
            if (A16) {
                const unsigned* Ap16 = As16 + st*128*20;
                #pragma unroll
                for (int mi = 0; mi < 2; mi++) {
                    int r = m0w + mi*16 + g;
                    af[mi][0] = Ap16[r*20 + 8*ks + tg];
                    af[mi][1] = Ap16[(r+8)*20 + 8*ks + tg];
                    af[mi][2] = Ap16[r*20 + 8*ks + tg + 4];
                    af[mi][3] = Ap16[(r+8)*20 + 8*ks + tg + 4];
                }
            } else {
                const float* Ap = As + st*128*A_PITCH;
                #pragma unroll
                for (int mi = 0; mi < 2; mi++) {
                    int r = m0w + mi*16 + g;
                    int kc = 16*ks + 2*tg;
                    float2 p00 = *(const float2*)&Ap[r*A_PITCH + kc];
                    float2 p01 = *(const float2*)&Ap[(r+8)*A_PITCH + kc];
                    float2 p10 = *(const float2*)&Ap[r*A_PITCH + kc + 8];
                    float2 p11 = *(const float2*)&Ap[(r+8)*A_PITCH + kc + 8];
                    af[mi][0] = packh2(p00.x, p00.y);
                    af[mi][1] = packh2(p01.x, p01.y);
                    af[mi][2] = packh2(p10.x, p10.y);
                    af[mi][3] = packh2(p11.x, p11.y);
                }
            }
            #pragma unroll
            for (int mi = 0; mi < 2; mi++)
                #pragma unroll
                for (int ni = 0; ni < 8; ni++) {
                    unsigned bf[2] = { bw0[ni], bw1[ni] };
                    mma_f16(c[mi][ni], af[mi], bf);
                }
        }

        st = (st == 2) ? 0 : st + 1;
        st2 = (st2 == 2) ? 0 : st2 + 1;
    }

    // epilogue (column mapping: ni -> n0w + ni*8 + g; validated R7/R11/R12/R13)
    #pragma unroll
    for (int mi = 0; mi < 2; mi++) {
        #pragma unroll
        for (int ni = 0; ni < 8; ni++) {
            int cc = col0 + n0w + ni*8 + 2*tg;
            float bx = bias[cc], by = bias[cc+1];
            float vx0 = (c[mi][ni][0] + bx) * scale;
            float vy0 = (c[mi][ni][1] + by) * scale;
            float vx1 = (c[mi][ni][2] + bx) * scale;
            float vy1 = (c[mi][ni][3] + by) * scale;
            int r0_ = row0 + m0w + mi*16 + g;

            if (mode == 0) {
                float* out = (float*)outv;
                *(float2*)&out[(size_t)r0_ * Dsz + cc]     = make_float2(vx0, vy0);
                *(float2*)&out[(size_t)(r0_+8) * Dsz + cc] = make_float2(vx1, vy1);
            } else if (mode == 1) {
                unsigned* o16 = (unsigned*)outv;
                int h_ = cc >> 6, dh = cc & (DHs-1);
                int b0_ = r0_ >> 11, s0 = r0_ & (Ssz-1);
                size_t base0 = (((size_t)(b0_*Hn + h_) * Ssz) + s0) * 32 + (dh >> 1);
                o16[base0]        = packh2(vx0, vy0);
                o16[base0 + 8*32] = packh2(vx1, vy1);
            } else if (mode == 2) {
                unsigned* o16 = (unsigned*)outv;
                int h_ = cc >> 6, dh = cc & (DHs-1);
                int b_ = r0_ >> 11, s0 = r0_ & (Ssz-1);
                int w = (((s0 & 63) >> 4) << 3) | (s0 & 7);
                int p0 = ((dh & 7) << 3) | (dh >> 3);
                size_t idx = ((size_t)(b_*Hn + h_) * (Ssz/2)
                              + ((size_t)(s0 >> 6) << 5) + w) * 64 + p0;
                o16[idx]     = packh2(vx0, vx1);
                o16[idx + 8] = packh2(vy0, vy1);
            } else {
                unsigned* o16 = (unsigned*)outv;
                int h_ = cc >> 6, dd = (cc & (DHs-1)) >> 1;
                int b0_ = r0_ >> 11;
                size_t base = ((size_t)(b0_*Hn + h_) * 32 + dd) * Ssz;
                o16[base + (r0_ & (Ssz-1))]     = packh2(vx0, vy0);
                o16[base + ((r0_+8) & (Ssz-1))] = packh2(vx1, vy1);
            }
        }
    }
}

// ---------------------------------------------------------------------------
// FP16 flash attention (R13 compute, validated), 3-stage pipeline with ONE
// __syncthreads per KV tile (same safety argument as the GEMM).
// ---------------------------------------------------------------------------
#define ATTN_SMEM (6*32*64*4)   // 49,152 B

__global__ __launch_bounds__(256, 2)
void attn_f16(const unsigned* __restrict__ Q16, const unsigned* __restrict__ K16,
              const unsigned* __restrict__ V16, unsigned* __restrict__ O16)
{
    extern __shared__ unsigned smu[];
    unsigned* Kt = smu;               // [3][32][64]
    unsigned* Vs = smu + 3*32*64;     // [3][32][64]

    const int tid  = threadIdx.x;
    const int lane = tid & 31;
    const int warp = tid >> 5;
    const int g  = lane >> 2;
    const int tg = lane & 3;
    const int r0 = warp * 16 + g;

    const int q0 = blockIdx.x * 128;
    const int h = blockIdx.y, b = blockIdx.z;
    const size_t bh = (size_t)(b*Hn + h);
    const unsigned* Qg = Q16 + bh * Ssz * 32;
    const unsigned* Kg = K16 + bh * 32 * Ssz;
    const unsigned* Vg = V16 + bh * (Ssz/2) * 64;

    const int sig = (tg & 1) | ((tg & 2) << 1);
    const int pk0 = ((2*g)     ^ sig) << 2;
    const int pk1 = ((2*g + 1) ^ sig) << 2;

    // ---- Q fragments: pre-packed words, 16 scalar LDG once ----
    unsigned aq[4][4];
    {
        const unsigned* Qw0 = &Qg[(size_t)(q0 + r0) * 32];
        const unsigned* Qw1 = &Qg[(size_t)(q0 + r0 + 8) * 32];
        #pragma unroll
        for (int ks = 0; ks < 4; ks++) {
            aq[ks][0] = Qw0[8*ks + tg];
            aq[ks][1] = Qw1[8*ks + tg];
            aq[ks][2] = Qw0[8*ks + tg + 4];
            aq[ks][3] = Qw1[8*ks + tg + 4];
        }
    }

    auto load_tile = [&](int t0, int stage) {
        unsigned* Kd = Kt + stage*32*64;
        unsigned* Vd = Vs + stage*32*64;
        #pragma unroll
        for (int i = 0; i < 2; i++) {
            int idx = tid + i*256;
            int w = idx >> 4, c = idx & 15;
            int sk = (w & 1) | ((w & 2) << 1);
            cp_async16(&Kd[w*64 + ((c ^ sk) << 2)],
                       &Kg[(size_t)w * Ssz + t0 + 4*c]);
            int sv = ((w >> 3) & 1) | (((w >> 3) & 2) << 1);
            cp_async16(&Vd[w*64 + ((c ^ sv) << 2)],
                       &Vg[(size_t)(((t0 >> 6) << 5) + w) * 64 + 4*c]);
        }
    };

    load_tile(0, 0);   CP_COMMIT();
    load_tile(64, 1);  CP_COMMIT();

    float o[8][4] = {};
    float m0 = -1e30f, m1 = -1e30f, l0 = 0.0f, l1 = 0.0f;

    const int NTILE = Ssz / 64;   // 32
    int st = 0, st2 = 2;
    for (int t = 0; t < NTILE; t++) {
        if (t + 1 < NTILE) { CP_WAIT1(); } else { CP_WAIT0(); }
        __syncthreads();

        if (t + 2 < NTILE) {
            load_tile((t+2)*64, st2);
            CP_COMMIT();
        }

        const unsigned* Ktp = Kt + st*32*64;
        const unsigned* Vsp = Vs + st*32*64;

        float s[8][4] = {};
        #pragma unroll
        for (int ks = 0; ks < 4; ks++) {
            unsigned bw0[8], bw1[8];
            const unsigned* Kr0 = &Ktp[(8*ks + tg)*64];
            const unsigned* Kr1 = &Ktp[(8*ks + tg + 4)*64];
            *(uint4*)&bw0[0] = *(const uint4*)&Kr0[pk0];
            *(uint4*)&bw0[4] = *(const uint4*)&Kr0[pk1];
            *(uint4*)&bw1[0] = *(const uint4*)&Kr1[pk0];
            *(uint4*)&bw1[4] = *(const uint4*)&Kr1[pk1];
            #pragma unroll
            for (int nt = 0; nt < 8; nt++) {
                unsigned bf[2] = { bw0[nt], bw1[nt] };
                mma_f16(s[nt], aq[ks], bf);
            }
        }

        float rm0 = -1e30f, rm1 = -1e30f;
        #pragma unroll
        for (int nt = 0; nt < 8; nt++) {
            rm0 = fmaxf(rm0, fmaxf(s[nt][0], s[nt][1]));
            rm1 = fmaxf(rm1, fmaxf(s[nt][2], s[nt][3]));
        }
        rm0 = fmaxf(rm0, __shfl_xor_sync(0xffffffffu, rm0, 1));
        rm0 = fmaxf(rm0, __shfl_xor_sync(0xffffffffu, rm0, 2));
        rm1 = fmaxf(rm1, __shfl_xor_sync(0xffffffffu, rm1, 1));
        rm1 = fmaxf(rm1, __shfl_xor_sync(0xffffffffu, rm1, 2));

        float mn0 = fmaxf(m0, rm0), mn1 = fmaxf(m1, rm1);
        float al0 = ex2(m0 - mn0), al1 = ex2(m1 - mn1);
        m0 = mn0; m1 = mn1;

        float rs0 = 0.0f, rs1 = 0.0f;
        #pragma unroll
        for (int nt = 0; nt < 8; nt++) {
            s[nt][0] = ex2(s[nt][0] - m0);
            s[nt][1] = ex2(s[nt][1] - m0);
            s[nt][2] = ex2(s[nt][2] - m1);
            s[nt][3] = ex2(s[nt][3] - m1);
            rs0 += s[nt][0] + s[nt][1];
            rs1 += s[nt][2] + s[nt][3];
        }
        rs0 += __shfl_xor_sync(0xffffffffu, rs0, 1);
        rs0 += __shfl_xor_sync(0xffffffffu, rs0, 2);
        rs1 += __shfl_xor_sync(0xffffffffu, rs1, 1);
        rs1 += __shfl_xor_sync(0xffffffffu, rs1, 2);

        l0 = l0 * al0 + rs0;
        l1 = l1 * al1 + rs1;
        #pragma unroll
        for (int nt = 0; nt < 8; nt++) {
            o[nt][0] *= al0; o[nt][1] *= al0;
            o[nt][2] *= al1; o[nt][3] *= al1;
        }

        unsigned pf[8][2];
        #pragma unroll
        for (int nt = 0; nt < 8; nt++) {
            pf[nt][0] = packh2(s[nt][0], s[nt][1]);
            pf[nt][1] = packh2(s[nt][2], s[nt][3]);
        }

        #pragma unroll
        for (int ks = 0; ks < 4; ks++) {
            unsigned bw0[8], bw1[8];
            const unsigned* Vr0 = &Vsp[(8*tg + 2*ks)*64];
            const unsigned* Vr1 = &Vsp[(8*tg + 2*ks + 1)*64];
            *(uint4*)&bw0[0] = *(const uint4*)&Vr0[pk0];
            *(uint4*)&bw0[4] = *(const uint4*)&Vr0[pk1];
            *(uint4*)&bw1[0] = *(const uint4*)&Vr1[pk0];
            *(uint4*)&bw1[4] = *(const uint4*)&Vr1[pk1];
            unsigned a[4] = { pf[2*ks][0], pf[2*ks][1], pf[2*ks+1][0], pf[2*ks+1][1] };
            #pragma unroll
            for (int nt = 0; nt < 8; nt++) {
                unsigned bf[2] = { bw0[nt], bw1[nt] };
                mma_f16(o[nt], a, bf);
            }
        }

        st = (st == 2) ? 0 : st + 1;
        st2 = (st2 == 2) ? 0 : st2 + 1;
    }

    // ---- normalize + write O as packed half2 words [M, 512w] ----
    float inv0 = 1.0f / l0, inv1 = 1.0f / l1;
    size_t ob0 = ((size_t)(b*Ssz + q0 + r0)) * (Dsz/2) + h*32;
    size_t ob1 = ((size_t)(b*Ssz + q0 + r0 + 8)) * (Dsz/2) + h*32;
    #pragma unroll
    for (int nt = 0; nt < 8; nt++) {
        int w = nt*4 + tg;
        O16[ob0 + w] = packh2(o[nt][0]*inv0, o[nt][1]*inv0);
        O16[ob1 + w] = packh2(o[nt][2]*inv1, o[nt][3]*inv1);
    }
}

// ---------------------------------------------------------------------------

extern "C" void kernel_launch(void* const* d_in, const int* in_sizes, int n_in,
                              void* d_out, int out_size)
{
    (void)in_sizes; (void)n_in; (void)out_size;
    const float* queries = (const float*)d_in[0];
    const float* keys    = (const float*)d_in[1];
    const float* values  = (const float*)d_in[2];
    const float* Wq = (const float*)d_in[3];
    const float* bq = (const float*)d_in[4];
    const float* Wk = (const float*)d_in[5];
    const float* bk = (const float*)d_in[6];
    const float* Wv = (const float*)d_in[7];
    const float* bv = (const float*)d_in[8];
    const float* Wo = (const float*)d_in[9];
    const float* bo = (const float*)d_in[10];
    float* out = (float*)d_out;

    void *pwq,*pwk,*pwv,*pwo,*pq,*pk,*pv,*po;
    cudaGetSymbolAddress(&pwq, g_wq16); cudaGetSymbolAddress(&pwk, g_wk16);
    cudaGetSymbolAddress(&pwv, g_wv16); cudaGetSymbolAddress(&pwo, g_wo16);
    cudaGetSymbolAddress(&pq, g_q16);   cudaGetSymbolAddress(&pk, g_k16);
    cudaGetSymbolAddress(&pv, g_v16);   cudaGetSymbolAddress(&po, g_o16);

    cudaFuncSetAttribute((const void*)gemm_f16m<0>, cudaFuncAttributeMaxDynamicSharedMemorySize, GEMM_SMEM);
    cudaFuncSetAttribute((const void*)gemm_f16m<1>, cudaFuncAttributeMaxDynamicSharedMemorySize, GEMM_SMEM16);
    cudaFuncSetAttribute((const void*)attn_f16,     cudaFuncAttributeMaxDynamicSharedMemorySize, ATTN_SMEM);

    // launch 1: all four weight converts
    cvt_w16x4<<<2048, 256>>>(Wq, Wk, Wv, Wo,
                             (unsigned*)pwq, (unsigned*)pwk,
                             (unsigned*)pwv, (unsigned*)pwo);

    const float qscale = 0.125f * 1.4426950408889634f;   // log2e / sqrt(64)

    // launch 2: merged Q/K/V projections (grid.z selects mode)
    GemmArgs qkv;
    qkv.X[0] = queries; qkv.X[1] = keys; qkv.X[2] = values;
    qkv.W[0] = (const unsigned*)pwq; qkv.W[1] = (const unsigned*)pwk; qkv.W[2] = (const unsigned*)pwv;
    qkv.bias[0] = bq; qkv.bias[1] = bk; qkv.bias[2] = bv;
    qkv.out[0] = pq; qkv.out[1] = pk; qkv.out[2] = pv;
    qkv.scale[0] = qscale; qkv.scale[1] = 1.0f; qkv.scale[2] = 1.0f;
    qkv.mode[0] = 1; qkv.mode[1] = 3; qkv.mode[2] = 2;
    dim3 qgrid(Dsz/128, Mrows/128, 3);   // (8, 32, 3)
    gemm_f16m<0><<<qgrid, 256, GEMM_SMEM>>>(qkv);

    // launch 3: attention
    dim3 agrid(Ssz/128, Hn, Bsz);        // (16, 16, 2)
    attn_f16<<<agrid, 256, ATTN_SMEM>>>((const unsigned*)pq, (const unsigned*)pk,
                                        (const unsigned*)pv, (unsigned*)po);

    // launch 4: final projection (pre-packed fp16 A path)
    GemmArgs fin;
    fin.X[0] = po; fin.X[1] = po; fin.X[2] = po;
    fin.W[0] = (const unsigned*)pwo; fin.W[1] = (const unsigned*)pwo; fin.W[2] = (const unsigned*)pwo;
    fin.bias[0] = bo; fin.bias[1] = bo; fin.bias[2] = bo;
    fin.out[0] = out; fin.out[1] = out; fin.out[2] = out;
    fin.scale[0] = 1.0f; fin.scale[1] = 1.0f; fin.scale[2] = 1.0f;
    fin.mode[0] = 0; fin.mode[1] = 0; fin.mode[2] = 0;
    dim3 fgrid(Dsz/128, Mrows/128, 1);
    gemm_f16m<1><<<fgrid, 256, GEMM_SMEM16>>>(fin);
}

// round 15
// speedup vs baseline: 2.2113x; 1.0222x over previous
#include <cuda_runtime.h>
#include <cuda_fp16.h>
#include <math.h>

#define Bsz 2
#define Ssz 2048
#define Dsz 1024
#define Hn  16
#define DHs 64
#define Mrows (Bsz*Ssz)

// Scratch (static device globals; no runtime allocation)
__device__ unsigned g_wq16[(Dsz/2)*Dsz];  // fp16-packed k-pairs, pi64 n-permute
__device__ unsigned g_wk16[(Dsz/2)*Dsz];
__device__ unsigned g_wv16[(Dsz/2)*Dsz];
__device__ unsigned g_wo16[(Dsz/2)*Dsz];
__device__ unsigned g_q16[Mrows*Dsz/2];    // [B,H,S,32w]
__device__ unsigned g_k16[Mrows*Dsz/2];    // [B,H,32(dd),S]
__device__ unsigned g_v16[Mrows*Dsz/2];    // [B,H,S/2(w),64]
__device__ unsigned g_o16[Mrows*Dsz/2];    // [M,512w]

// ---------------------------------------------------------------------------
// helpers
// ---------------------------------------------------------------------------
__device__ __forceinline__ float ex2(float x) {
    float r; asm("ex2.approx.ftz.f32 %0, %1;" : "=f"(r) : "f"(x)); return r;
}
__device__ __forceinline__ unsigned packh2(float lo, float hi) {
    __half2 h = __floats2half2_rn(lo, hi);
    return *reinterpret_cast<unsigned*>(&h);
}
__device__ __forceinline__ void mma_f16(float* c, const unsigned* a, const unsigned* b) {
    asm volatile(
        "mma.sync.aligned.m16n8k16.row.col.f32.f16.f16.f32 "
        "{%0,%1,%2,%3}, {%4,%5,%6,%7}, {%8,%9}, {%0,%1,%2,%3};"
        : "+f"(c[0]), "+f"(c[1]), "+f"(c[2]), "+f"(c[3])
        : "r"(a[0]), "r"(a[1]), "r"(a[2]), "r"(a[3]), "r"(b[0]), "r"(b[1]));
}
__device__ __forceinline__ void cp_async16(void* smem, const void* gmem) {
    unsigned s = (unsigned)__cvta_generic_to_shared(smem);
    asm volatile("cp.async.cg.shared.global [%0], [%1], 16;" :: "r"(s), "l"(gmem));
}
#define CP_COMMIT() asm volatile("cp.async.commit_group;")
#define CP_WAIT1()  asm volatile("cp.async.wait_group 1;")
#define CP_WAIT0()  asm volatile("cp.async.wait_group 0;")

// ---------------------------------------------------------------------------
// Weight convert, all four in one launch (R13/R14, validated).
// ---------------------------------------------------------------------------
__global__ void cvt_w16x4(const float* __restrict__ s0, const float* __restrict__ s1,
                          const float* __restrict__ s2, const float* __restrict__ s3,
                          unsigned* __restrict__ d0, unsigned* __restrict__ d1,
                          unsigned* __restrict__ d2, unsigned* __restrict__ d3)
{
    int wsel = blockIdx.x >> 9;
    const float* in = (wsel == 0) ? s0 : (wsel == 1) ? s1 : (wsel == 2) ? s2 : s3;
    unsigned* out   = (wsel == 0) ? d0 : (wsel == 1) ? d1 : (wsel == 2) ? d2 : d3;
    int gid = (blockIdx.x & 511) * 256 + threadIdx.x;
    int kk = gid >> 8;
    int n  = (gid & 255) * 4;
    float4 v0 = *(const float4*)&in[(size_t)(2*kk)     * Dsz + n];
    float4 v1 = *(const float4*)&in[(size_t)(2*kk + 1) * Dsz + n];
    float a0[4] = {v0.x, v0.y, v0.z, v0.w};
    float a1[4] = {v1.x, v1.y, v1.z, v1.w};
    size_t base = (size_t)kk * Dsz + (n & ~63);
    #pragma unroll
    for (int i = 0; i < 4; i++) {
        int x = (n & 63) + i;
        int p = ((x & 7) << 3) | (x >> 3);
        out[base + p] = packh2(a0[i], a1[i]);
    }
}

// ---------------------------------------------------------------------------
// FP16 GEMM, BK=64 per iteration, 2-stage cp.async pipeline, ONE
// __syncthreads per iteration (16 total), post-sync prefetch (race-free:
// the sync proves all warps finished computing buffer p^1 before overwrite).
// Fragment/epilogue algebra byte-compatible with R13/R14 (validated);
// ks now spans 0..3 within a 64-wide k-window (same k order -> identical FP).
// Pads re-derived: A-fp32 pitch 72 (8g+2tg banks, distinct); A16 pitch 52
// words (20g+tg covers all 32 banks); B swizzle classes use row bits 0-1 only.
// ---------------------------------------------------------------------------
struct GemmArgs {
    const void*     X[3];
    const unsigned* W[3];
    const float*    bias[3];
    void*           out[3];
    float           scale[3];
    int             mode[3];
};

#define APF 72                                        // fp32-A pitch (floats)
#define APW 52                                        // packed-A pitch (words)
#define GEMM_SMEM   (2*(128*APF + 32*128) * 4)        // 106,496 B
#define GEMM_SMEM16 (2*(128*APW + 32*128) * 4)        //  86,016 B

template<int A16>
__global__ __launch_bounds__(256, 2)
void gemm_f16m(GemmArgs args)
{
    extern __shared__ float sm[];
    const int APITCH = A16 ? APW : APF;
    float*    As   = sm;                              // [2][128][APITCH]
    unsigned* As16 = (unsigned*)sm;
    unsigned* Bs   = (unsigned*)(sm + 2*128*APITCH);  // [2][32][128]

    const int z = blockIdx.z;
    const void*     Xv   = args.X[z];
    const unsigned* Wh   = args.W[z];
    const float*    bias = args.bias[z];
    void*           outv = args.out[z];
    const float     scale = args.scale[z];
    const int       mode  = args.mode[z];

    const int tid  = threadIdx.x;
    const int lane = tid & 31;
    const int warp = tid >> 5;
    const int g  = lane >> 2;
    const int tg = lane & 3;
    const int m0w = (warp >> 1) * 32;
    const int n0w = (warp & 1) * 64;
    const int row0 = blockIdx.y * 128;
    const int col0 = blockIdx.x * 128;

    const int sB = ((tg & 1) << 2) | ((tg >> 1) & 1);
    const int cb = (n0w >> 2) + 2*g;

    float c[2][8][4] = {};

    auto load_stage = [&](int kt, int st) {           // kt in 64-wide units
        unsigned* Bd = Bs + st*32*128;
        if (A16) {
            unsigned* Ad = As16 + st*128*APW;
            const unsigned* X16 = (const unsigned*)Xv;
            #pragma unroll
            for (int i = 0; i < 4; i++) {
                int idx = tid + i*256;
                int r = idx >> 3, wc = idx & 7;
                cp_async16(&Ad[r*APW + wc*4],
                           &X16[(size_t)(row0 + r)*(Dsz/2) + kt*32 + wc*4]);
            }
        } else {
            float* Ad = As + st*128*APF;
            const float* X = (const float*)Xv;
            #pragma unroll
            for (int i = 0; i < 8; i++) {
                int idx = tid + i*256;
                int r = idx >> 4, c4 = idx & 15;
                cp_async16(&Ad[r*APF + c4*4],
                           &X[(size_t)(row0 + r)*Dsz + kt*64 + c4*4]);
            }
        }
        #pragma unroll
        for (int i = 0; i < 4; i++) {
            int idx = tid + i*256;
            int r = idx >> 5, cc = idx & 31;
            int s = ((r & 1) << 2) | ((r >> 1) & 1);
            cp_async16(&Bd[r*128 + ((cc ^ s) << 2)],
                       &Wh[(size_t)(kt*32 + r)*Dsz + col0 + (cc << 2)]);
        }
    };

    load_stage(0, 0);
    CP_COMMIT();

    const int NT = Dsz / 64;   // 16
    for (int kt = 0; kt < NT; kt++) {
        int p = kt & 1;
        CP_WAIT0();
        __syncthreads();                 // stage p ready; all warps done with p^1
        if (kt + 1 < NT) {
            load_stage(kt + 1, p ^ 1);   // overlaps compute below
            CP_COMMIT();
        }

        const unsigned* Bp = Bs + p*32*128;
        #pragma unroll
        for (int ks = 0; ks < 4; ks++) {
            unsigned bw0[8], bw1[8];
            {
                const unsigned* Br0 = &Bp[(8*ks + tg) * 128];
                const unsigned* Br1 = &Bp[(8*ks + tg + 4) * 128];
                *(uint4*)&bw0[0] = *(const uint4*)&Br0[((cb)     ^ sB) << 2];
                *(uint4*)&bw0[4] = *(const uint4*)&Br0[((cb + 1) ^ sB) << 2];
                *(uint4*)&bw1[0] = *(const uint4*)&Br1[((cb)     ^ sB) << 2];
                *(uint4*)&bw1[4] = *(const uint4*)&Br1[((cb + 1) ^ sB) << 2];
            }
            unsigned af[2][4];
            if (A16) {
                const unsigned* Ap16 = As16 + p*128*APW;
                #pragma unroll
                for (int mi = 0; mi < 2; mi++) {
                    int r = m0w + mi*16 + g;
                    af[mi][0] = Ap16[r*APW + 8*ks + tg];
                    af[mi][1] = Ap16[(r+8)*APW + 8*ks + tg];
                    af[mi][2] = Ap16[r*APW + 8*ks + tg + 4];
                    af[mi][3] = Ap16[(r+8)*APW + 8*ks + tg + 4];
                }
            } else {
                const float* Ap = As + p*128*APF;
                #pragma unroll
                for (int mi = 0; mi < 2; mi++) {
                    int r = m0w + mi*16 + g;
                    int kc = 16*ks + 2*tg;
                    float2 p00 = *(const float2*)&Ap[r*APF + kc];
                    float2 p01 = *(const float2*)&Ap[(r+8)*APF + kc];
                    float2 p10 = *(const float2*)&Ap[r*APF + kc + 8];
                    float2 p11 = *(const float2*)&Ap[(r+8)*APF + kc + 8];
                    af[mi][0] = packh2(p00.x, p00.y);
                    af[mi][1] = packh2(p01.x, p01.y);
                    af[mi][2] = packh2(p10.x, p10.y);
                    af[mi][3] = packh2(p11.x, p11.y);
                }
            }
            #pragma unroll
            for (int mi = 0; mi < 2; mi++)
                #pragma unroll
                for (int ni = 0; ni < 8; ni++) {
                    unsigned bf[2] = { bw0[ni], bw1[ni] };
                    mma_f16(c[mi][ni], af[mi], bf);
                }
        }
    }

    // epilogue (column mapping: ni -> n0w + ni*8 + g; validated R7/R11-R14)
    #pragma unroll
    for (int mi = 0; mi < 2; mi++) {
        #pragma unroll
        for (int ni = 0; ni < 8; ni++) {
            int cc = col0 + n0w + ni*8 + 2*tg;
            float bx = bias[cc], by = bias[cc+1];
            float vx0 = (c[mi][ni][0] + bx) * scale;
            float vy0 = (c[mi][ni][1] + by) * scale;
            float vx1 = (c[mi][ni][2] + bx) * scale;
            float vy1 = (c[mi][ni][3] + by) * scale;
            int r0_ = row0 + m0w + mi*16 + g;

            if (mode == 0) {
                float* out = (float*)outv;
                *(float2*)&out[(size_t)r0_ * Dsz + cc]     = make_float2(vx0, vy0);
                *(float2*)&out[(size_t)(r0_+8) * Dsz + cc] = make_float2(vx1, vy1);
            } else if (mode == 1) {
                unsigned* o16 = (unsigned*)outv;
                int h_ = cc >> 6, dh = cc & (DHs-1);
                int b0_ = r0_ >> 11, s0 = r0_ & (Ssz-1);
                size_t base0 = (((size_t)(b0_*Hn + h_) * Ssz) + s0) * 32 + (dh >> 1);
                o16[base0]        = packh2(vx0, vy0);
                o16[base0 + 8*32] = packh2(vx1, vy1);
            } else if (mode == 2) {
                unsigned* o16 = (unsigned*)outv;
                int h_ = cc >> 6, dh = cc & (DHs-1);
                int b_ = r0_ >> 11, s0 = r0_ & (Ssz-1);
                int w = (((s0 & 63) >> 4) << 3) | (s0 & 7);
                int p0 = ((dh & 7) << 3) | (dh >> 3);
                size_t idx = ((size_t)(b_*Hn + h_) * (Ssz/2)
                              + ((size_t)(s0 >> 6) << 5) + w) * 64 + p0;
                o16[idx]     = packh2(vx0, vx1);
                o16[idx + 8] = packh2(vy0, vy1);
            } else {
                unsigned* o16 = (unsigned*)outv;
                int h_ = cc >> 6, dd = (cc & (DHs-1)) >> 1;
                int b0_ = r0_ >> 11;
                size_t base = ((size_t)(b0_*Hn + h_) * 32 + dd) * Ssz;
                o16[base + (r0_ & (Ssz-1))]     = packh2(vx0, vy0);
                o16[base + ((r0_+8) & (Ssz-1))] = packh2(vx1, vy1);
            }
        }
    }
}

// ---------------------------------------------------------------------------
// FP16 flash attention — UNCHANGED from R14 (measured-good, at fp16 roofline).
// ---------------------------------------------------------------------------
#define ATTN_SMEM (6*32*64*4)   // 49,152 B

__global__ __launch_bounds__(256, 2)
void attn_f16(const unsigned* __restrict__ Q16, const unsigned* __restrict__ K16,
              const unsigned* __restrict__ V16, unsigned* __restrict__ O16)
{
    extern __shared__ unsigned smu[];
    unsigned* Kt = smu;               // [3][32][64]
    unsigned* Vs = smu + 3*32*64;     // [3][32][64]

    const int tid  = threadIdx.x;
    const int lane = tid & 31;
    const int warp = tid >> 5;
    const int g  = lane >> 2;
    const int tg = lane & 3;
    const int r0 = warp * 16 + g;

    const int q0 = blockIdx.x * 128;
    const int h = blockIdx.y, b = blockIdx.z;
    const size_t bh = (size_t)(b*Hn + h);
    const unsigned* Qg = Q16 + bh * Ssz * 32;
    const unsigned* Kg = K16 + bh * 32 * Ssz;
    const unsigned* Vg = V16 + bh * (Ssz/2) * 64;

    const int sig = (tg & 1) | ((tg & 2) << 1);
    const int pk0 = ((2*g)     ^ sig) << 2;
    const int pk1 = ((2*g + 1) ^ sig) << 2;

    unsigned aq[4][4];
    {
        const unsigned* Qw0 = &Qg[(size_t)(q0 + r0) * 32];
        const unsigned* Qw1 = &Qg[(size_t)(q0 + r0 + 8) * 32];
        #pragma unroll
        for (int ks = 0; ks < 4; ks++) {
            aq[ks][0] = Qw0[8*ks + tg];
            aq[ks][1] = Qw1[8*ks + tg];
            aq[ks][2] = Qw0[8*ks + tg + 4];
            aq[ks][3] = Qw1[8*ks + tg + 4];
        }
    }

    auto load_tile = [&](int t0, int stage) {
        unsigned* Kd = Kt + stage*32*64;
        unsigned* Vd = Vs + stage*32*64;
        #pragma unroll
        for (int i = 0; i < 2; i++) {
            int idx = tid + i*256;
            int w = idx >> 4, c = idx & 15;
            int sk = (w & 1) | ((w & 2) << 1);
            cp_async16(&Kd[w*64 + ((c ^ sk) << 2)],
                       &Kg[(size_t)w * Ssz + t0 + 4*c]);
            int sv = ((w >> 3) & 1) | (((w >> 3) & 2) << 1);
            cp_async16(&Vd[w*64 + ((c ^ sv) << 2)],
                       &Vg[(size_t)(((t0 >> 6) << 5) + w) * 64 + 4*c]);
        }
    };

    load_tile(0, 0);   CP_COMMIT();
    load_tile(64, 1);  CP_COMMIT();

    float o[8][4] = {};
    float m0 = -1e30f, m1 = -1e30f, l0 = 0.0f, l1 = 0.0f;

    const int NTILE = Ssz / 64;   // 32
    int st = 0, st2 = 2;
    for (int t = 0; t < NTILE; t++) {
        if (t + 1 < NTILE) { CP_WAIT1(); } else { CP_WAIT0(); }
        __syncthreads();

        if (t + 2 < NTILE) {
            load_tile((t+2)*64, st2);
            CP_COMMIT();
        }

        const unsigned* Ktp = Kt + st*32*64;
        const unsigned* Vsp = Vs + st*32*64;

        float s[8][4] = {};
        #pragma unroll
        for (int ks = 0; ks < 4; ks++) {
            unsigned bw0[8], bw1[8];
            const unsigned* Kr0 = &Ktp[(8*ks + tg)*64];
            const unsigned* Kr1 = &Ktp[(8*ks + tg + 4)*64];
            *(uint4*)&bw0[0] = *(const uint4*)&Kr0[pk0];
            *(uint4*)&bw0[4] = *(const uint4*)&Kr0[pk1];
            *(uint4*)&bw1[0] = *(const uint4*)&Kr1[pk0];
            *(uint4*)&bw1[4] = *(const uint4*)&Kr1[pk1];
            #pragma unroll
            for (int nt = 0; nt < 8; nt++) {
                unsigned bf[2] = { bw0[nt], bw1[nt] };
                mma_f16(s[nt], aq[ks], bf);
            }
        }

        float rm0 = -1e30f, rm1 = -1e30f;
        #pragma unroll
        for (int nt = 0; nt < 8; nt++) {
            rm0 = fmaxf(rm0, fmaxf(s[nt][0], s[nt][1]));
            rm1 = fmaxf(rm1, fmaxf(s[nt][2], s[nt][3]));
        }
        rm0 = fmaxf(rm0, __shfl_xor_sync(0xffffffffu, rm0, 1));
        rm0 = fmaxf(rm0, __shfl_xor_sync(0xffffffffu, rm0, 2));
        rm1 = fmaxf(rm1, __shfl_xor_sync(0xffffffffu, rm1, 1));
        rm1 = fmaxf(rm1, __shfl_xor_sync(0xffffffffu, rm1, 2));

        float mn0 = fmaxf(m0, rm0), mn1 = fmaxf(m1, rm1);
        float al0 = ex2(m0 - mn0), al1 = ex2(m1 - mn1);
        m0 = mn0; m1 = mn1;

        float rs0 = 0.0f, rs1 = 0.0f;
        #pragma unroll
        for (int nt = 0; nt < 8; nt++) {
            s[nt][0] = ex2(s[nt][0] - m0);
            s[nt][1] = ex2(s[nt][1] - m0);
            s[nt][2] = ex2(s[nt][2] - m1);
            s[nt][3] = ex2(s[nt][3] - m1);
            rs0 += s[nt][0] + s[nt][1];
            rs1 += s[nt][2] + s[nt][3];
        }
        rs0 += __shfl_xor_sync(0xffffffffu, rs0, 1);
        rs0 += __shfl_xor_sync(0xffffffffu, rs0, 2);
        rs1 += __shfl_xor_sync(0xffffffffu, rs1, 1);
        rs1 += __shfl_xor_sync(0xffffffffu, rs1, 2);

        l0 = l0 * al0 + rs0;
        l1 = l1 * al1 + rs1;
        #pragma unroll
        for (int nt = 0; nt < 8; nt++) {
            o[nt][0] *= al0; o[nt][1] *= al0;
            o[nt][2] *= al1; o[nt][3] *= al1;
        }

        unsigned pf[8][2];
        #pragma unroll
        for (int nt = 0; nt < 8; nt++) {
            pf[nt][0] = packh2(s[nt][0], s[nt][1]);
            pf[nt][1] = packh2(s[nt][2], s[nt][3]);
        }

        #pragma unroll
        for (int ks = 0; ks < 4; ks++) {
            unsigned bw0[8], bw1[8];
            const unsigned* Vr0 = &Vsp[(8*tg + 2*ks)*64];
            const unsigned* Vr1 = &Vsp[(8*tg + 2*ks + 1)*64];
            *(uint4*)&bw0[0] = *(const uint4*)&Vr0[pk0];
            *(uint4*)&bw0[4] = *(const uint4*)&Vr0[pk1];
            *(uint4*)&bw1[0] = *(const uint4*)&Vr1[pk0];
            *(uint4*)&bw1[4] = *(const uint4*)&Vr1[pk1];
            unsigned a[4] = { pf[2*ks][0], pf[2*ks][1], pf[2*ks+1][0], pf[2*ks+1][1] };
            #pragma unroll
            for (int nt = 0; nt < 8; nt++) {
                unsigned bf[2] = { bw0[nt], bw1[nt] };
                mma_f16(o[nt], a, bf);
            }
        }

        st = (st == 2) ? 0 : st + 1;
        st2 = (st2 == 2) ? 0 : st2 + 1;
    }

    float inv0 = 1.0f / l0, inv1 = 1.0f / l1;
    size_t ob0 = ((size_t)(b*Ssz + q0 + r0)) * (Dsz/2) + h*32;
    size_t ob1 = ((size_t)(b*Ssz + q0 + r0 + 8)) * (Dsz/2) + h*32;
    #pragma unroll
    for (int nt = 0; nt < 8; nt++) {
        int w = nt*4 + tg;
        O16[ob0 + w] = packh2(o[nt][0]*inv0, o[nt][1]*inv0);
        O16[ob1 + w] = packh2(o[nt][2]*inv1, o[nt][3]*inv1);
    }
}

// ---------------------------------------------------------------------------

extern "C" void kernel_launch(void* const* d_in, const int* in_sizes, int n_in,
                              void* d_out, int out_size)
{
    (void)in_sizes; (void)n_in; (void)out_size;
    const float* queries = (const float*)d_in[0];
    const float* keys    = (const float*)d_in[1];
    const float* values  = (const float*)d_in[2];
    const float* Wq = (const float*)d_in[3];
    const float* bq = (const float*)d_in[4];
    const float* Wk = (const float*)d_in[5];
    const float* bk = (const float*)d_in[6];
    const float* Wv = (const float*)d_in[7];
    const float* bv = (const float*)d_in[8];
    const float* Wo = (const float*)d_in[9];
    const float* bo = (const float*)d_in[10];
    float* out = (float*)d_out;

    void *pwq,*pwk,*pwv,*pwo,*pq,*pk,*pv,*po;
    cudaGetSymbolAddress(&pwq, g_wq16); cudaGetSymbolAddress(&pwk, g_wk16);
    cudaGetSymbolAddress(&pwv, g_wv16); cudaGetSymbolAddress(&pwo, g_wo16);
    cudaGetSymbolAddress(&pq, g_q16);   cudaGetSymbolAddress(&pk, g_k16);
    cudaGetSymbolAddress(&pv, g_v16);   cudaGetSymbolAddress(&po, g_o16);

    cudaFuncSetAttribute((const void*)gemm_f16m<0>, cudaFuncAttributeMaxDynamicSharedMemorySize, GEMM_SMEM);
    cudaFuncSetAttribute((const void*)gemm_f16m<1>, cudaFuncAttributeMaxDynamicSharedMemorySize, GEMM_SMEM16);
    cudaFuncSetAttribute((const void*)attn_f16,     cudaFuncAttributeMaxDynamicSharedMemorySize, ATTN_SMEM);

    // launch 1: all four weight converts
    cvt_w16x4<<<2048, 256>>>(Wq, Wk, Wv, Wo,
                             (unsigned*)pwq, (unsigned*)pwk,
                             (unsigned*)pwv, (unsigned*)pwo);

    const float qscale = 0.125f * 1.4426950408889634f;   // log2e / sqrt(64)

    // launch 2: merged Q/K/V projections (grid.z selects mode)
    GemmArgs qkv;
    qkv.X[0] = queries; qkv.X[1] = keys; qkv.X[2] = values;
    qkv.W[0] = (const unsigned*)pwq; qkv.W[1] = (const unsigned*)pwk; qkv.W[2] = (const unsigned*)pwv;
    qkv.bias[0] = bq; qkv.bias[1] = bk; qkv.bias[2] = bv;
    qkv.out[0] = pq; qkv.out[1] = pk; qkv.out[2] = pv;
    qkv.scale[0] = qscale; qkv.scale[1] = 1.0f; qkv.scale[2] = 1.0f;
    qkv.mode[0] = 1; qkv.mode[1] = 3; qkv.mode[2] = 2;
    dim3 qgrid(Dsz/128, Mrows/128, 3);   // (8, 32, 3)
    gemm_f16m<0><<<qgrid, 256, GEMM_SMEM>>>(qkv);

    // launch 3: attention
    dim3 agrid(Ssz/128, Hn, Bsz);        // (16, 16, 2)
    attn_f16<<<agrid, 256, ATTN_SMEM>>>((const unsigned*)pq, (const unsigned*)pk,
                                        (const unsigned*)pv, (unsigned*)po);

    // launch 4: final projection (pre-packed fp16 A path)
    GemmArgs fin;
    fin.X[0] = po; fin.X[1] = po; fin.X[2] = po;
    fin.W[0] = (const unsigned*)pwo; fin.W[1] = (const unsigned*)pwo; fin.W[2] = (const unsigned*)pwo;
    fin.bias[0] = bo; fin.bias[1] = bo; fin.bias[2] = bo;
    fin.out[0] = out; fin.out[1] = out; fin.out[2] = out;
    fin.scale[0] = 1.0f; fin.scale[1] = 1.0f; fin.scale[2] = 1.0f;
    fin.mode[0] = 0; fin.mode[1] = 0; fin.mode[2] = 0;
    dim3 fgrid(Dsz/128, Mrows/128, 1);
    gemm_f16m<1><<<fgrid, 256, GEMM_SMEM16>>>(fin);
}